// round 8
// baseline (speedup 1.0000x reference)
#include <cuda_runtime.h>
#include <cuda_bf16.h>
#include <math.h>
#include <stdint.h>

// Problem constants
#define BB 2
#define SS 2048
#define DD 1024
#define HH 16
#define HDIM 64
#define II 3752
#define MROWS (BB*SS)          // 4096
#define EPS 1e-6f
#define FULLMASK 0xffffffffu
#define LDQKV (3*DD)           // 3072

// ---------------- scratch (device globals) ----------------
__device__ float g_h   [MROWS * DD];
__device__ float g_qkv [MROWS * LDQKV];
__device__ float g_att [MROWS * DD];
__device__ float g_res1[MROWS * DD];
__device__ float g_h2  [MROWS * DD];
__device__ float g_gate[MROWS * II];
__device__ float g_act [MROWS * II];
__device__ float g_cw  [4 * DD * DD + 3 * DD * II];
__device__ float g_bcat[LDQKV];

#define CW_QKV 0
#define CW_O  (3*DD*DD)
#define CW_G  (4*DD*DD)
#define CW_U  (4*DD*DD + DD*II)
#define CW_D  (4*DD*DD + 2*DD*II)

// ---------------- tf32 helpers ----------------
__device__ __forceinline__ uint32_t f2tf32(float f) {
    uint32_t r;
    asm("cvt.rna.tf32.f32 %0, %1;" : "=r"(r) : "f"(f));
    return r;
}
__device__ __forceinline__ float tf32r(float f) { return __uint_as_float(f2tf32(f)); }

__device__ __forceinline__ void mma_tf32(float* d, const uint32_t* a, const uint32_t* b) {
    asm("mma.sync.aligned.m16n8k8.row.col.f32.tf32.tf32.f32 "
        "{%0,%1,%2,%3},{%4,%5,%6,%7},{%8,%9},{%0,%1,%2,%3};"
        : "+f"(d[0]), "+f"(d[1]), "+f"(d[2]), "+f"(d[3])
        : "r"(a[0]), "r"(a[1]), "r"(a[2]), "r"(a[3]), "r"(b[0]), "r"(b[1]));
}

#define CP_ASYNC(dst, src, sz) \
    asm volatile("cp.async.cg.shared.global [%0], [%1], 16, %2;\n" :: "r"(dst), "l"(src), "r"(sz))
#define CP_COMMIT asm volatile("cp.async.commit_group;\n" ::)
#define CP_WAIT1  asm volatile("cp.async.wait_group 1;\n" ::)

// ---------------- weight converts (RN-round to tf32 once per replay) --------
// one kernel for wo / w_gate / w_up / w_down
__global__ void cvt_all_kernel(const float* __restrict__ wo, const float* __restrict__ wg,
                               const float* __restrict__ wu, const float* __restrict__ wd,
                               float* __restrict__ cw)
{
    const int N_O = DD * DD / 4;          // float4 counts
    const int N_I = DD * II / 4;
    int i = blockIdx.x * 256 + threadIdx.x;
    const float* src; float* dst; int j;
    if (i < N_O)                  { src = wo; dst = cw + CW_O; j = i; }
    else if (i < N_O + N_I)       { src = wg; dst = cw + CW_G; j = i - N_O; }
    else if (i < N_O + 2 * N_I)   { src = wu; dst = cw + CW_U; j = i - N_O - N_I; }
    else if (i < N_O + 3 * N_I)   { src = wd; dst = cw + CW_D; j = i - N_O - 2 * N_I; }
    else return;
    float4 v = ((const float4*)src)[j];
    v.x = tf32r(v.x); v.y = tf32r(v.y); v.z = tf32r(v.z); v.w = tf32r(v.w);
    ((float4*)dst)[j] = v;
}

// QKV: round + scatter into concat layout [K=1024][N=3072]
__global__ void cvt_qkv_kernel(const float* __restrict__ wq, const float* __restrict__ wk,
                               const float* __restrict__ wv, float* __restrict__ dst)
{
    const int PER = DD * DD / 4;
    int i = blockIdx.x * 256 + threadIdx.x;
    int which = i / PER;
    int j = i - which * PER;
    const float* src = (which == 0) ? wq : (which == 1) ? wk : wv;
    float4 v = ((const float4*)src)[j];
    v.x = tf32r(v.x); v.y = tf32r(v.y); v.z = tf32r(v.z); v.w = tf32r(v.w);
    int k = j >> 8;
    int n4 = j & 255;
    ((float4*)dst)[k * (LDQKV/4) + which * (DD/4) + n4] = v;
}

__global__ void bcat_kernel(const float* __restrict__ bq, const float* __restrict__ bk,
                            const float* __restrict__ bv, float* __restrict__ dst)
{
    int i = blockIdx.x * 256 + threadIdx.x;
    if (i < LDQKV) {
        int which = i >> 10, j = i & 1023;
        dst[i] = (which == 0) ? bq[j] : (which == 1) ? bk[j] : bv[j];
    }
}

// ---------------- RMSNorm (output tf32-rounded) ----------------
__global__ void rmsnorm_kernel(const float* __restrict__ x, const float* __restrict__ w,
                               float* __restrict__ out)
{
    int row = blockIdx.x;
    const float* xr = x + (size_t)row * DD;
    float sum = 0.f;
    for (int c = threadIdx.x; c < DD; c += 256) { float t = xr[c]; sum += t * t; }
    __shared__ float red[256];
    red[threadIdx.x] = sum;
    __syncthreads();
    for (int s = 128; s > 0; s >>= 1) {
        if (threadIdx.x < s) red[threadIdx.x] += red[threadIdx.x + s];
        __syncthreads();
    }
    float r = rsqrtf(red[0] * (1.0f / DD) + EPS);
    float* orow = out + (size_t)row * DD;
    for (int c = threadIdx.x; c < DD; c += 256) orow[c] = tf32r(w[c] * (xr[c] * r));
}

// ---------------- pipelined tf32 GEMM: 256x128 block, 512 thr, warp 64x32 ----
#define GBM 256
#define GBN 128
#define GBK 16
#define NTHR 512
#define ASTRIDE 20
#define BSTRIDE 136
#define ASZ (GBM*ASTRIDE)      // 5120
#define BSZ (GBK*BSTRIDE)      // 2176
#define STG (ASZ+BSZ)          // 7296 floats per stage
#define GEMM_SMEM_BYTES (3*STG*4)   // 87552

__device__ __forceinline__ void gemm_load_stage(
    const float* __restrict__ A, const float* __restrict__ W,
    int N, int K, int bm, int bn, int k0, float* sA, float* sB, int tid)
{
    // A tile: 256 rows x 16 k = 1024 float4; 512 threads -> 2 each
    #pragma unroll
    for (int u = 0; u < 2; u++) {
        int id = tid + u * NTHR;
        int row = id >> 2, cc = (id & 3) * 4;
        int kk = k0 + cc;
        int sz = (kk + 4 <= K) ? 16 : 0;
        const float* src = A + (size_t)(bm + row) * K + (sz ? kk : 0);
        uint32_t dst = (uint32_t)__cvta_generic_to_shared(sA + row * ASTRIDE + cc);
        CP_ASYNC(dst, src, sz);
    }
    // B tile: 16 rows x 128 cols = 512 float4; 1 each
    {
        int row = tid >> 5, cc = (tid & 31) * 4;
        int kk = k0 + row, col = bn + cc;
        int sz = (kk < K && col + 4 <= N) ? 16 : 0;
        const float* src = W + (sz ? ((size_t)kk * N + col) : 0);
        uint32_t dst = (uint32_t)__cvta_generic_to_shared(sB + row * BSTRIDE + cc);
        CP_ASYNC(dst, src, sz);
    }
}

__global__ __launch_bounds__(NTHR) void gemm_tf32_kernel(
    const float* __restrict__ A, const float* __restrict__ W,
    const float* __restrict__ bias, const float* __restrict__ res,
    const float* __restrict__ gate, float* __restrict__ C,
    int M, int N, int K, int roundout)
{
    extern __shared__ float smem[];

    const int tid  = threadIdx.x;
    const int lane = tid & 31;
    const int warp = tid >> 5;          // 0..15
    const int wm = warp >> 2;           // 0..3 -> 64 rows each
    const int wn = warp & 3;            // 0..3 -> 32 cols each
    const int grp = lane >> 2;
    const int tig = lane & 3;

    const int bm = blockIdx.y * GBM;
    const int bn = blockIdx.x * GBN;

    float acc[4][4][4];
    #pragma unroll
    for (int i = 0; i < 4; i++)
        #pragma unroll
        for (int j = 0; j < 4; j++)
            #pragma unroll
            for (int r = 0; r < 4; r++) acc[i][j][r] = 0.f;

    const int T = (K + GBK - 1) / GBK;

    gemm_load_stage(A, W, N, K, bm, bn, 0, smem, smem + ASZ, tid);
    CP_COMMIT;
    gemm_load_stage(A, W, N, K, bm, bn, GBK, smem + STG, smem + STG + ASZ, tid);
    CP_COMMIT;

    for (int t = 0; t < T; t++) {
        CP_WAIT1;
        __syncthreads();

        const float* sA = smem + (t % 3) * STG;
        const float* sB = sA + ASZ;

        #pragma unroll
        for (int ks = 0; ks < 2; ks++) {
            const int kb = ks * 8;
            uint32_t af[4][4];
            #pragma unroll
            for (int mt = 0; mt < 4; mt++) {
                const float* p = sA + (wm * 64 + mt * 16 + grp) * ASTRIDE + kb + tig;
                af[mt][0] = __float_as_uint(p[0]);
                af[mt][1] = __float_as_uint(p[8 * ASTRIDE]);
                af[mt][2] = __float_as_uint(p[4]);
                af[mt][3] = __float_as_uint(p[8 * ASTRIDE + 4]);
            }
            uint32_t bf[4][2];
            #pragma unroll
            for (int nt = 0; nt < 4; nt++) {
                const float* p = sB + (kb + tig) * BSTRIDE + wn * 32 + nt * 8 + grp;
                bf[nt][0] = __float_as_uint(p[0]);
                bf[nt][1] = __float_as_uint(p[4 * BSTRIDE]);
            }
            #pragma unroll
            for (int mt = 0; mt < 4; mt++)
                #pragma unroll
                for (int nt = 0; nt < 4; nt++)
                    mma_tf32(acc[mt][nt], af[mt], bf[nt]);
        }

        if (t + 2 < T) {
            float* dA = smem + ((t + 2) % 3) * STG;
            gemm_load_stage(A, W, N, K, bm, bn, (t + 2) * GBK, dA, dA + ASZ, tid);
        }
        CP_COMMIT;
    }

    // ---- epilogue ----
    #pragma unroll
    for (int mt = 0; mt < 4; mt++) {
        int r0 = bm + wm * 64 + mt * 16 + grp;
        #pragma unroll
        for (int nt = 0; nt < 4; nt++) {
            int c0 = bn + wn * 32 + nt * 8 + 2 * tig;
            if (c0 >= N) continue;
            float v0 = acc[mt][nt][0], v1 = acc[mt][nt][1];
            float v2 = acc[mt][nt][2], v3 = acc[mt][nt][3];
            if (bias) {
                float b0 = bias[c0], b1 = bias[c0 + 1];
                v0 += b0; v1 += b1; v2 += b0; v3 += b1;
            }
            if (gate) {
                float2 ga = *(const float2*)&gate[(size_t)r0 * N + c0];
                float2 gb = *(const float2*)&gate[(size_t)(r0 + 8) * N + c0];
                v0 *= ga.x / (1.0f + __expf(-ga.x));
                v1 *= ga.y / (1.0f + __expf(-ga.y));
                v2 *= gb.x / (1.0f + __expf(-gb.x));
                v3 *= gb.y / (1.0f + __expf(-gb.y));
            }
            if (res) {
                float2 ra = *(const float2*)&res[(size_t)r0 * N + c0];
                float2 rb = *(const float2*)&res[(size_t)(r0 + 8) * N + c0];
                v0 += ra.x; v1 += ra.y; v2 += rb.x; v3 += rb.y;
            }
            if (roundout) { v0 = tf32r(v0); v1 = tf32r(v1); v2 = tf32r(v2); v3 = tf32r(v3); }
            *(float2*)&C[(size_t)r0 * N + c0]       = make_float2(v0, v1);
            *(float2*)&C[(size_t)(r0 + 8) * N + c0] = make_float2(v2, v3);
        }
    }
}

// ---------------- flash attention (tf32 mma, online softmax) ----------------
// q,k,v in fused [M, 3072] buffer (pre-rounded tf32); row stride LDQKV.
#define ATT_STRIDE 72
#define ATT_SMEM_BYTES ((64*ATT_STRIDE*2 + 128*ATT_STRIDE) * 4)

__global__ __launch_bounds__(256, 1) void attn_kernel(
    const float* __restrict__ qkv, float* __restrict__ out)
{
    extern __shared__ float smem[];
    float* sK  = smem;
    float* sV  = smem + 64 * ATT_STRIDE;
    float* sQP = smem + 128 * ATT_STRIDE;

    const int tid  = threadIdx.x;
    const int lane = tid & 31;
    const int warp = tid >> 5;
    const int grp  = lane >> 2;
    const int tig  = lane & 3;

    const int q0 = blockIdx.x * 128;
    const int h  = blockIdx.y;
    const int b  = blockIdx.z;

    const float slope = -exp2f(-0.5f * (float)(h + 1));

    const float* qbase = qkv + (size_t)(b * SS + q0) * LDQKV + h * HDIM;
    #pragma unroll
    for (int it = 0; it < 8; it++) {
        int idx = it * 256 + tid;
        int r = idx >> 4, c4 = (idx & 15) * 4;
        *(float4*)&sQP[r * ATT_STRIDE + c4] = *(const float4*)&qbase[(size_t)r * LDQKV + c4];
    }
    __syncthreads();

    const int myr = warp * 16 + grp;
    uint32_t qf[8][4];
    #pragma unroll
    for (int ks = 0; ks < 8; ks++) {
        qf[ks][0] = __float_as_uint(0.125f * sQP[(myr    ) * ATT_STRIDE + ks * 8 + tig    ]);
        qf[ks][1] = __float_as_uint(0.125f * sQP[(myr + 8) * ATT_STRIDE + ks * 8 + tig    ]);
        qf[ks][2] = __float_as_uint(0.125f * sQP[(myr    ) * ATT_STRIDE + ks * 8 + tig + 4]);
        qf[ks][3] = __float_as_uint(0.125f * sQP[(myr + 8) * ATT_STRIDE + ks * 8 + tig + 4]);
    }
    __syncthreads();

    const int row0 = q0 + warp * 16 + grp;
    const int row1 = row0 + 8;
    const int warp_max_row = q0 + warp * 16 + 15;

    float m0 = -INFINITY, m1 = -INFINITY, l0 = 0.f, l1 = 0.f;
    float oacc[8][4];
    #pragma unroll
    for (int nt = 0; nt < 8; nt++)
        #pragma unroll
        for (int r = 0; r < 4; r++) oacc[nt][r] = 0.f;

    const int nkt = (q0 >> 6) + 2;
    const float* kbase0 = qkv + (size_t)(b * SS) * LDQKV + DD     + h * HDIM;
    const float* vbase0 = qkv + (size_t)(b * SS) * LDQKV + 2 * DD + h * HDIM;

    for (int kt = 0; kt < nkt; kt++) {
        const int j0 = kt * 64;
        const float* kb_ = kbase0 + (size_t)j0 * LDQKV;
        const float* vb_ = vbase0 + (size_t)j0 * LDQKV;
        #pragma unroll
        for (int it = 0; it < 4; it++) {
            int idx = it * 256 + tid;
            int r = idx >> 4, c4 = (idx & 15) * 4;
            *(float4*)&sK[r * ATT_STRIDE + c4] = *(const float4*)&kb_[(size_t)r * LDQKV + c4];
            *(float4*)&sV[r * ATT_STRIDE + c4] = *(const float4*)&vb_[(size_t)r * LDQKV + c4];
        }
        __syncthreads();

        if (j0 <= warp_max_row) {
            float sacc[8][4];
            #pragma unroll
            for (int nt = 0; nt < 8; nt++)
                #pragma unroll
                for (int r = 0; r < 4; r++) sacc[nt][r] = 0.f;

            #pragma unroll
            for (int ks = 0; ks < 8; ks++) {
                uint32_t bf[8][2];
                #pragma unroll
                for (int nt = 0; nt < 8; nt++) {
                    bf[nt][0] = __float_as_uint(sK[(nt * 8 + grp) * ATT_STRIDE + ks * 8 + tig    ]);
                    bf[nt][1] = __float_as_uint(sK[(nt * 8 + grp) * ATT_STRIDE + ks * 8 + tig + 4]);
                }
                #pragma unroll
                for (int nt = 0; nt < 8; nt++)
                    mma_tf32(sacc[nt], qf[ks], bf[nt]);
            }

            float mn0 = m0, mn1 = m1;
            #pragma unroll
            for (int nt = 0; nt < 8; nt++) {
                int cbase = j0 + nt * 8 + 2 * tig;
                #pragma unroll
                for (int r = 0; r < 4; r++) {
                    int col = cbase + (r & 1);
                    int rw = (r < 2) ? row0 : row1;
                    float s;
                    if (col > rw) s = -INFINITY;
                    else          s = sacc[nt][r] + slope * (float)(rw - col);
                    sacc[nt][r] = s;
                    if (r < 2) mn0 = fmaxf(mn0, s); else mn1 = fmaxf(mn1, s);
                }
            }
            mn0 = fmaxf(mn0, __shfl_xor_sync(FULLMASK, mn0, 1));
            mn0 = fmaxf(mn0, __shfl_xor_sync(FULLMASK, mn0, 2));
            mn1 = fmaxf(mn1, __shfl_xor_sync(FULLMASK, mn1, 1));
            mn1 = fmaxf(mn1, __shfl_xor_sync(FULLMASK, mn1, 2));

            float f0 = __expf(m0 - mn0);
            float f1 = __expf(m1 - mn1);
            m0 = mn0; m1 = mn1;

            float rs0 = 0.f, rs1 = 0.f;
            #pragma unroll
            for (int nt = 0; nt < 8; nt++) {
                float p0 = __expf(sacc[nt][0] - m0);
                float p1 = __expf(sacc[nt][1] - m0);
                float p2 = __expf(sacc[nt][2] - m1);
                float p3 = __expf(sacc[nt][3] - m1);
                sacc[nt][0] = p0; sacc[nt][1] = p1; sacc[nt][2] = p2; sacc[nt][3] = p3;
                rs0 += p0 + p1; rs1 += p2 + p3;
            }
            rs0 += __shfl_xor_sync(FULLMASK, rs0, 1);
            rs0 += __shfl_xor_sync(FULLMASK, rs0, 2);
            rs1 += __shfl_xor_sync(FULLMASK, rs1, 1);
            rs1 += __shfl_xor_sync(FULLMASK, rs1, 2);
            l0 = l0 * f0 + rs0;
            l1 = l1 * f1 + rs1;

            #pragma unroll
            for (int nt = 0; nt < 8; nt++) {
                oacc[nt][0] *= f0; oacc[nt][1] *= f0;
                oacc[nt][2] *= f1; oacc[nt][3] *= f1;
            }

            #pragma unroll
            for (int nt = 0; nt < 8; nt++) {
                *(float2*)&sQP[(myr    ) * ATT_STRIDE + nt * 8 + 2 * tig] = make_float2(sacc[nt][0], sacc[nt][1]);
                *(float2*)&sQP[(myr + 8) * ATT_STRIDE + nt * 8 + 2 * tig] = make_float2(sacc[nt][2], sacc[nt][3]);
            }
            __syncwarp();

            #pragma unroll
            for (int ks = 0; ks < 8; ks++) {
                uint32_t pf[4];
                pf[0] = f2tf32(sQP[(myr    ) * ATT_STRIDE + ks * 8 + tig    ]);
                pf[1] = f2tf32(sQP[(myr + 8) * ATT_STRIDE + ks * 8 + tig    ]);
                pf[2] = f2tf32(sQP[(myr    ) * ATT_STRIDE + ks * 8 + tig + 4]);
                pf[3] = f2tf32(sQP[(myr + 8) * ATT_STRIDE + ks * 8 + tig + 4]);
                uint32_t vf[8][2];
                #pragma unroll
                for (int nt = 0; nt < 8; nt++) {
                    vf[nt][0] = __float_as_uint(sV[(ks * 8 + tig    ) * ATT_STRIDE + nt * 8 + grp]);
                    vf[nt][1] = __float_as_uint(sV[(ks * 8 + tig + 4) * ATT_STRIDE + nt * 8 + grp]);
                }
                #pragma unroll
                for (int nt = 0; nt < 8; nt++)
                    mma_tf32(oacc[nt], pf, vf[nt]);
            }
        }
        __syncthreads();
    }

    float inv0 = 1.0f / l0, inv1 = 1.0f / l1;
    float* obase = out + (size_t)(b * SS) * DD + h * HDIM;
    #pragma unroll
    for (int nt = 0; nt < 8; nt++) {
        int d = nt * 8 + 2 * tig;
        *(float2*)&obase[(size_t)row0 * DD + d] =
            make_float2(tf32r(oacc[nt][0] * inv0), tf32r(oacc[nt][1] * inv0));
        *(float2*)&obase[(size_t)row1 * DD + d] =
            make_float2(tf32r(oacc[nt][2] * inv1), tf32r(oacc[nt][3] * inv1));
    }
}

// ---------------- launch ----------------
extern "C" void kernel_launch(void* const* d_in, const int* in_sizes, int n_in,
                              void* d_out, int out_size)
{
    const float* x      = (const float*)d_in[0];
    const float* wq     = (const float*)d_in[1];
    const float* bq     = (const float*)d_in[2];
    const float* wk     = (const float*)d_in[3];
    const float* bk     = (const float*)d_in[4];
    const float* wv     = (const float*)d_in[5];
    const float* bv     = (const float*)d_in[6];
    const float* wo     = (const float*)d_in[7];
    const float* bo     = (const float*)d_in[8];
    const float* w_gate = (const float*)d_in[9];
    const float* w_up   = (const float*)d_in[10];
    const float* w_down = (const float*)d_in[11];
    const float* ln1w   = (const float*)d_in[12];
    const float* ln2w   = (const float*)d_in[13];
    float* out = (float*)d_out;

    static float *pH = nullptr, *pQKV, *pAtt, *pRes1, *pH2, *pGate, *pAct, *pCW, *pBcat;
    if (!pH) {
        cudaGetSymbolAddress((void**)&pH,    g_h);
        cudaGetSymbolAddress((void**)&pQKV,  g_qkv);
        cudaGetSymbolAddress((void**)&pAtt,  g_att);
        cudaGetSymbolAddress((void**)&pRes1, g_res1);
        cudaGetSymbolAddress((void**)&pH2,   g_h2);
        cudaGetSymbolAddress((void**)&pGate, g_gate);
        cudaGetSymbolAddress((void**)&pAct,  g_act);
        cudaGetSymbolAddress((void**)&pCW,   g_cw);
        cudaGetSymbolAddress((void**)&pBcat, g_bcat);
        cudaFuncSetAttribute(attn_kernel, cudaFuncAttributeMaxDynamicSharedMemorySize, ATT_SMEM_BYTES);
        cudaFuncSetAttribute(gemm_tf32_kernel, cudaFuncAttributeMaxDynamicSharedMemorySize, GEMM_SMEM_BYTES);
    }

    // 0. weight prep (RN rounding — required)
    const int nDD4 = DD * DD / 4, nDI4 = DD * II / 4;
    cvt_qkv_kernel<<<3 * nDD4 / 256, 256>>>(wq, wk, wv, pCW + CW_QKV);
    bcat_kernel<<<(LDQKV + 255) / 256, 256>>>(bq, bk, bv, pBcat);
    cvt_all_kernel<<<(nDD4 + 3 * nDI4 + 255) / 256, 256>>>(wo, w_gate, w_up, w_down, pCW);

    dim3 blk(NTHR);
    const int RND = 1, NORND = 0;

    // 1. h = rmsnorm(x) (tf32)
    rmsnorm_kernel<<<MROWS, 256>>>(x, ln1w, pH);

    // 2. fused QKV projection (N=3072, tf32 out)
    dim3 gQKV(LDQKV / GBN, MROWS / GBM);               // 24 x 16
    gemm_tf32_kernel<<<gQKV, blk, GEMM_SMEM_BYTES>>>(pH, pCW + CW_QKV, pBcat, nullptr, nullptr, pQKV, MROWS, LDQKV, DD, RND);

    // 3. flash attention
    dim3 ga(SS / 128, HH, BB);
    attn_kernel<<<ga, 256, ATT_SMEM_BYTES>>>(pQKV, pAtt);

    // 4. res1 = att @ wo + bo + x
    dim3 gD(DD / GBN, MROWS / GBM);                    // 8 x 16 = 128 CTAs (single wave)
    gemm_tf32_kernel<<<gD, blk, GEMM_SMEM_BYTES>>>(pAtt, pCW + CW_O, bo, x, nullptr, pRes1, MROWS, DD, DD, NORND);

    // 5. h2 = rmsnorm(res1) (tf32)
    rmsnorm_kernel<<<MROWS, 256>>>(pRes1, ln2w, pH2);

    // 6. gate = h2 @ w_gate
    dim3 gI((II + GBN - 1) / GBN, MROWS / GBM);        // 30 x 16
    gemm_tf32_kernel<<<gI, blk, GEMM_SMEM_BYTES>>>(pH2, pCW + CW_G, nullptr, nullptr, nullptr, pGate, MROWS, II, DD, NORND);

    // 7. act = silu(gate) * (h2 @ w_up) (tf32)
    gemm_tf32_kernel<<<gI, blk, GEMM_SMEM_BYTES>>>(pH2, pCW + CW_U, nullptr, nullptr, pGate, pAct, MROWS, II, DD, RND);

    // 8. out = act @ w_down + res1
    gemm_tf32_kernel<<<gD, blk, GEMM_SMEM_BYTES>>>(pAct, pCW + CW_D, nullptr, pRes1, nullptr, out, MROWS, DD, II, NORND);
}

// round 10
// speedup vs baseline: 1.1556x; 1.1556x over previous
#include <cuda_runtime.h>
#include <cuda_bf16.h>
#include <math.h>
#include <stdint.h>

// Problem constants
#define BB 2
#define SS 2048
#define DD 1024
#define HH 16
#define HDIM 64
#define II 3752
#define MROWS (BB*SS)          // 4096
#define EPS 1e-6f
#define FULLMASK 0xffffffffu
#define LDQKV (3*DD)           // 3072

// ---------------- scratch (device globals) ----------------
__device__ float g_h   [MROWS * DD];
__device__ float g_qkv [MROWS * LDQKV];
__device__ float g_att [MROWS * DD];
__device__ float g_res1[MROWS * DD];
__device__ float g_h2  [MROWS * DD];
__device__ float g_gate[MROWS * II];
__device__ float g_act [MROWS * II];
__device__ float g_cw  [4 * DD * DD + 3 * DD * II];
__device__ float g_bcat[LDQKV];

#define CW_QKV 0
#define CW_O  (3*DD*DD)
#define CW_G  (4*DD*DD)
#define CW_U  (4*DD*DD + DD*II)
#define CW_D  (4*DD*DD + 2*DD*II)

// ---------------- tf32 helpers ----------------
__device__ __forceinline__ uint32_t f2tf32(float f) {
    uint32_t r;
    asm("cvt.rna.tf32.f32 %0, %1;" : "=r"(r) : "f"(f));
    return r;
}
__device__ __forceinline__ float tf32r(float f) { return __uint_as_float(f2tf32(f)); }

__device__ __forceinline__ void mma_tf32(float* d, const uint32_t* a, const uint32_t* b) {
    asm("mma.sync.aligned.m16n8k8.row.col.f32.tf32.tf32.f32 "
        "{%0,%1,%2,%3},{%4,%5,%6,%7},{%8,%9},{%0,%1,%2,%3};"
        : "+f"(d[0]), "+f"(d[1]), "+f"(d[2]), "+f"(d[3])
        : "r"(a[0]), "r"(a[1]), "r"(a[2]), "r"(a[3]), "r"(b[0]), "r"(b[1]));
}

#define CP_ASYNC(dst, src, sz) \
    asm volatile("cp.async.cg.shared.global [%0], [%1], 16, %2;\n" :: "r"(dst), "l"(src), "r"(sz))
#define CP_COMMIT asm volatile("cp.async.commit_group;\n" ::)
#define CP_WAIT2  asm volatile("cp.async.wait_group 2;\n" ::)

// ---------------- weight converts (RN-round to tf32 once per replay) --------
__global__ void cvt_all_kernel(const float* __restrict__ wo, const float* __restrict__ wg,
                               const float* __restrict__ wu, const float* __restrict__ wd,
                               float* __restrict__ cw)
{
    const int N_O = DD * DD / 4;
    const int N_I = DD * II / 4;
    int i = blockIdx.x * 256 + threadIdx.x;
    const float* src; float* dst; int j;
    if (i < N_O)                  { src = wo; dst = cw + CW_O; j = i; }
    else if (i < N_O + N_I)       { src = wg; dst = cw + CW_G; j = i - N_O; }
    else if (i < N_O + 2 * N_I)   { src = wu; dst = cw + CW_U; j = i - N_O - N_I; }
    else if (i < N_O + 3 * N_I)   { src = wd; dst = cw + CW_D; j = i - N_O - 2 * N_I; }
    else return;
    float4 v = ((const float4*)src)[j];
    v.x = tf32r(v.x); v.y = tf32r(v.y); v.z = tf32r(v.z); v.w = tf32r(v.w);
    ((float4*)dst)[j] = v;
}

__global__ void cvt_qkv_kernel(const float* __restrict__ wq, const float* __restrict__ wk,
                               const float* __restrict__ wv, float* __restrict__ dst)
{
    const int PER = DD * DD / 4;
    int i = blockIdx.x * 256 + threadIdx.x;
    int which = i / PER;
    int j = i - which * PER;
    const float* src = (which == 0) ? wq : (which == 1) ? wk : wv;
    float4 v = ((const float4*)src)[j];
    v.x = tf32r(v.x); v.y = tf32r(v.y); v.z = tf32r(v.z); v.w = tf32r(v.w);
    int k = j >> 8;
    int n4 = j & 255;
    ((float4*)dst)[k * (LDQKV/4) + which * (DD/4) + n4] = v;
}

__global__ void bcat_kernel(const float* __restrict__ bq, const float* __restrict__ bk,
                            const float* __restrict__ bv, float* __restrict__ dst)
{
    int i = blockIdx.x * 256 + threadIdx.x;
    if (i < LDQKV) {
        int which = i >> 10, j = i & 1023;
        dst[i] = (which == 0) ? bq[j] : (which == 1) ? bk[j] : bv[j];
    }
}

// ---------------- RMSNorm (single pass, output tf32-rounded) ----------------
// 256 threads, each owns exactly one float4 of the 1024-wide row.
__global__ void rmsnorm_kernel(const float* __restrict__ x, const float* __restrict__ w,
                               float* __restrict__ out)
{
    int row = blockIdx.x;
    int tid = threadIdx.x;
    float4 v = ((const float4*)(x + (size_t)row * DD))[tid];
    float sum = v.x * v.x + v.y * v.y + v.z * v.z + v.w * v.w;

    __shared__ float red[256];
    // warp reduce then cross-warp
    #pragma unroll
    for (int s = 16; s > 0; s >>= 1) sum += __shfl_xor_sync(FULLMASK, sum, s);
    if ((tid & 31) == 0) red[tid >> 5] = sum;
    __syncthreads();
    if (tid < 8) {
        float t = red[tid];
        #pragma unroll
        for (int s = 4; s > 0; s >>= 1) t += __shfl_xor_sync(0xFF, t, s);
        if (tid == 0) red[0] = t;
    }
    __syncthreads();
    float r = rsqrtf(red[0] * (1.0f / DD) + EPS);

    float4 wv = ((const float4*)w)[tid];
    float4 o;
    o.x = tf32r(wv.x * (v.x * r));
    o.y = tf32r(wv.y * (v.y * r));
    o.z = tf32r(wv.z * (v.z * r));
    o.w = tf32r(wv.w * (v.w * r));
    ((float4*)(out + (size_t)row * DD))[tid] = o;
}

// ---------------- pipelined tf32 GEMM: 128x128 block, warp 64x32, 4-stage ----
#define GBM 128
#define GBN 128
#define GBK 16
#define NSTG 4
#define ASTRIDE 20
#define BSTRIDE 136
#define ASZ (GBM*ASTRIDE)
#define BSZ (GBK*BSTRIDE)
#define STG (ASZ+BSZ)
#define GEMM_SMEM_BYTES (NSTG*STG*4)

__device__ __forceinline__ void gemm_load_stage(
    const float* __restrict__ A, const float* __restrict__ W,
    int N, int K, int bm, int bn, int k0, float* sA, float* sB, int tid)
{
    #pragma unroll
    for (int u = 0; u < 2; u++) {
        int id = tid + u * 256;
        int row = id >> 2, cc = (id & 3) * 4;
        int kk = k0 + cc;
        int sz = (kk + 4 <= K) ? 16 : 0;
        const float* src = A + (size_t)(bm + row) * K + (sz ? kk : 0);
        uint32_t dst = (uint32_t)__cvta_generic_to_shared(sA + row * ASTRIDE + cc);
        CP_ASYNC(dst, src, sz);
    }
    #pragma unroll
    for (int u = 0; u < 2; u++) {
        int id = tid + u * 256;
        int row = id >> 5, cc = (id & 31) * 4;
        int kk = k0 + row, col = bn + cc;
        int sz = (kk < K && col + 4 <= N) ? 16 : 0;
        const float* src = W + (sz ? ((size_t)kk * N + col) : 0);
        uint32_t dst = (uint32_t)__cvta_generic_to_shared(sB + row * BSTRIDE + cc);
        CP_ASYNC(dst, src, sz);
    }
}

__global__ __launch_bounds__(256) void gemm_tf32_kernel(
    const float* __restrict__ A, const float* __restrict__ W,
    const float* __restrict__ bias, const float* __restrict__ res,
    const float* __restrict__ gate, float* __restrict__ C,
    int M, int N, int K, int roundout)
{
    extern __shared__ float smem[];

    const int tid  = threadIdx.x;
    const int lane = tid & 31;
    const int warp = tid >> 5;
    const int wm = warp >> 2;
    const int wn = warp & 3;
    const int grp = lane >> 2;
    const int tig = lane & 3;

    const int bm = blockIdx.y * GBM;
    const int bn = blockIdx.x * GBN;

    float acc[4][4][4];
    #pragma unroll
    for (int i = 0; i < 4; i++)
        #pragma unroll
        for (int j = 0; j < 4; j++)
            #pragma unroll
            for (int r = 0; r < 4; r++) acc[i][j][r] = 0.f;

    const int T = (K + GBK - 1) / GBK;

    // prefetch 3 stages
    #pragma unroll
    for (int s = 0; s < 3; s++) {
        gemm_load_stage(A, W, N, K, bm, bn, s * GBK, smem + s * STG, smem + s * STG + ASZ, tid);
        CP_COMMIT;
    }

    for (int t = 0; t < T; t++) {
        CP_WAIT2;
        __syncthreads();

        const float* sA = smem + (t % NSTG) * STG;
        const float* sB = sA + ASZ;

        #pragma unroll
        for (int ks = 0; ks < 2; ks++) {
            const int kb = ks * 8;
            uint32_t af[4][4];
            #pragma unroll
            for (int mt = 0; mt < 4; mt++) {
                const float* p = sA + (wm * 64 + mt * 16 + grp) * ASTRIDE + kb + tig;
                af[mt][0] = __float_as_uint(p[0]);
                af[mt][1] = __float_as_uint(p[8 * ASTRIDE]);
                af[mt][2] = __float_as_uint(p[4]);
                af[mt][3] = __float_as_uint(p[8 * ASTRIDE + 4]);
            }
            uint32_t bf[4][2];
            #pragma unroll
            for (int nt = 0; nt < 4; nt++) {
                const float* p = sB + (kb + tig) * BSTRIDE + wn * 32 + nt * 8 + grp;
                bf[nt][0] = __float_as_uint(p[0]);
                bf[nt][1] = __float_as_uint(p[4 * BSTRIDE]);
            }
            #pragma unroll
            for (int mt = 0; mt < 4; mt++)
                #pragma unroll
                for (int nt = 0; nt < 4; nt++)
                    mma_tf32(acc[mt][nt], af[mt], bf[nt]);
        }

        if (t + 3 < T) {
            float* dA = smem + ((t + 3) % NSTG) * STG;
            gemm_load_stage(A, W, N, K, bm, bn, (t + 3) * GBK, dA, dA + ASZ, tid);
        }
        CP_COMMIT;
    }

    // ---- epilogue ----
    #pragma unroll
    for (int mt = 0; mt < 4; mt++) {
        int r0 = bm + wm * 64 + mt * 16 + grp;
        #pragma unroll
        for (int nt = 0; nt < 4; nt++) {
            int c0 = bn + wn * 32 + nt * 8 + 2 * tig;
            if (c0 >= N) continue;
            float v0 = acc[mt][nt][0], v1 = acc[mt][nt][1];
            float v2 = acc[mt][nt][2], v3 = acc[mt][nt][3];
            if (bias) {
                float b0 = bias[c0], b1 = bias[c0 + 1];
                v0 += b0; v1 += b1; v2 += b0; v3 += b1;
            }
            if (gate) {
                float2 ga = *(const float2*)&gate[(size_t)r0 * N + c0];
                float2 gb = *(const float2*)&gate[(size_t)(r0 + 8) * N + c0];
                v0 *= ga.x / (1.0f + __expf(-ga.x));
                v1 *= ga.y / (1.0f + __expf(-ga.y));
                v2 *= gb.x / (1.0f + __expf(-gb.x));
                v3 *= gb.y / (1.0f + __expf(-gb.y));
            }
            if (res) {
                float2 ra = *(const float2*)&res[(size_t)r0 * N + c0];
                float2 rb = *(const float2*)&res[(size_t)(r0 + 8) * N + c0];
                v0 += ra.x; v1 += ra.y; v2 += rb.x; v3 += rb.y;
            }
            if (roundout) { v0 = tf32r(v0); v1 = tf32r(v1); v2 = tf32r(v2); v3 = tf32r(v3); }
            *(float2*)&C[(size_t)r0 * N + c0]       = make_float2(v0, v1);
            *(float2*)&C[(size_t)(r0 + 8) * N + c0] = make_float2(v2, v3);
        }
    }
}

// ---------------- flash attention (tf32 mma, online softmax) ----------------
#define ATT_STRIDE 72
#define ATT_SMEM_BYTES ((64*ATT_STRIDE*2 + 128*ATT_STRIDE) * 4)

__global__ __launch_bounds__(256, 1) void attn_kernel(
    const float* __restrict__ qkv, float* __restrict__ out)
{
    extern __shared__ float smem[];
    float* sK  = smem;
    float* sV  = smem + 64 * ATT_STRIDE;
    float* sQP = smem + 128 * ATT_STRIDE;

    const int tid  = threadIdx.x;
    const int lane = tid & 31;
    const int warp = tid >> 5;
    const int grp  = lane >> 2;
    const int tig  = lane & 3;

    // LPT: heavy (high-q0) blocks launch first
    const int qb = gridDim.x - 1 - blockIdx.x;
    const int q0 = qb * 128;
    const int h  = blockIdx.y;
    const int b  = blockIdx.z;

    const float slope = -exp2f(-0.5f * (float)(h + 1));

    const float* qbase = qkv + (size_t)(b * SS + q0) * LDQKV + h * HDIM;
    #pragma unroll
    for (int it = 0; it < 8; it++) {
        int idx = it * 256 + tid;
        int r = idx >> 4, c4 = (idx & 15) * 4;
        *(float4*)&sQP[r * ATT_STRIDE + c4] = *(const float4*)&qbase[(size_t)r * LDQKV + c4];
    }
    __syncthreads();

    const int myr = warp * 16 + grp;
    uint32_t qf[8][4];
    #pragma unroll
    for (int ks = 0; ks < 8; ks++) {
        qf[ks][0] = __float_as_uint(0.125f * sQP[(myr    ) * ATT_STRIDE + ks * 8 + tig    ]);
        qf[ks][1] = __float_as_uint(0.125f * sQP[(myr + 8) * ATT_STRIDE + ks * 8 + tig    ]);
        qf[ks][2] = __float_as_uint(0.125f * sQP[(myr    ) * ATT_STRIDE + ks * 8 + tig + 4]);
        qf[ks][3] = __float_as_uint(0.125f * sQP[(myr + 8) * ATT_STRIDE + ks * 8 + tig + 4]);
    }
    __syncthreads();

    const int row0 = q0 + warp * 16 + grp;
    const int row1 = row0 + 8;
    const int warp_max_row = q0 + warp * 16 + 15;

    float m0 = -INFINITY, m1 = -INFINITY, l0 = 0.f, l1 = 0.f;
    float oacc[8][4];
    #pragma unroll
    for (int nt = 0; nt < 8; nt++)
        #pragma unroll
        for (int r = 0; r < 4; r++) oacc[nt][r] = 0.f;

    const int nkt = (q0 >> 6) + 2;
    const float* kbase0 = qkv + (size_t)(b * SS) * LDQKV + DD     + h * HDIM;
    const float* vbase0 = qkv + (size_t)(b * SS) * LDQKV + 2 * DD + h * HDIM;

    for (int kt = 0; kt < nkt; kt++) {
        const int j0 = kt * 64;
        const float* kb_ = kbase0 + (size_t)j0 * LDQKV;
        const float* vb_ = vbase0 + (size_t)j0 * LDQKV;
        #pragma unroll
        for (int it = 0; it < 4; it++) {
            int idx = it * 256 + tid;
            int r = idx >> 4, c4 = (idx & 15) * 4;
            *(float4*)&sK[r * ATT_STRIDE + c4] = *(const float4*)&kb_[(size_t)r * LDQKV + c4];
            *(float4*)&sV[r * ATT_STRIDE + c4] = *(const float4*)&vb_[(size_t)r * LDQKV + c4];
        }
        __syncthreads();

        if (j0 <= warp_max_row) {
            float sacc[8][4];
            #pragma unroll
            for (int nt = 0; nt < 8; nt++)
                #pragma unroll
                for (int r = 0; r < 4; r++) sacc[nt][r] = 0.f;

            #pragma unroll
            for (int ks = 0; ks < 8; ks++) {
                uint32_t bf[8][2];
                #pragma unroll
                for (int nt = 0; nt < 8; nt++) {
                    bf[nt][0] = __float_as_uint(sK[(nt * 8 + grp) * ATT_STRIDE + ks * 8 + tig    ]);
                    bf[nt][1] = __float_as_uint(sK[(nt * 8 + grp) * ATT_STRIDE + ks * 8 + tig + 4]);
                }
                #pragma unroll
                for (int nt = 0; nt < 8; nt++)
                    mma_tf32(sacc[nt], qf[ks], bf[nt]);
            }

            float mn0 = m0, mn1 = m1;
            #pragma unroll
            for (int nt = 0; nt < 8; nt++) {
                int cbase = j0 + nt * 8 + 2 * tig;
                #pragma unroll
                for (int r = 0; r < 4; r++) {
                    int col = cbase + (r & 1);
                    int rw = (r < 2) ? row0 : row1;
                    float s;
                    if (col > rw) s = -INFINITY;
                    else          s = sacc[nt][r] + slope * (float)(rw - col);
                    sacc[nt][r] = s;
                    if (r < 2) mn0 = fmaxf(mn0, s); else mn1 = fmaxf(mn1, s);
                }
            }
            mn0 = fmaxf(mn0, __shfl_xor_sync(FULLMASK, mn0, 1));
            mn0 = fmaxf(mn0, __shfl_xor_sync(FULLMASK, mn0, 2));
            mn1 = fmaxf(mn1, __shfl_xor_sync(FULLMASK, mn1, 1));
            mn1 = fmaxf(mn1, __shfl_xor_sync(FULLMASK, mn1, 2));

            float f0 = __expf(m0 - mn0);
            float f1 = __expf(m1 - mn1);
            m0 = mn0; m1 = mn1;

            float rs0 = 0.f, rs1 = 0.f;
            #pragma unroll
            for (int nt = 0; nt < 8; nt++) {
                float p0 = __expf(sacc[nt][0] - m0);
                float p1 = __expf(sacc[nt][1] - m0);
                float p2 = __expf(sacc[nt][2] - m1);
                float p3 = __expf(sacc[nt][3] - m1);
                sacc[nt][0] = p0; sacc[nt][1] = p1; sacc[nt][2] = p2; sacc[nt][3] = p3;
                rs0 += p0 + p1; rs1 += p2 + p3;
            }
            rs0 += __shfl_xor_sync(FULLMASK, rs0, 1);
            rs0 += __shfl_xor_sync(FULLMASK, rs0, 2);
            rs1 += __shfl_xor_sync(FULLMASK, rs1, 1);
            rs1 += __shfl_xor_sync(FULLMASK, rs1, 2);
            l0 = l0 * f0 + rs0;
            l1 = l1 * f1 + rs1;

            #pragma unroll
            for (int nt = 0; nt < 8; nt++) {
                oacc[nt][0] *= f0; oacc[nt][1] *= f0;
                oacc[nt][2] *= f1; oacc[nt][3] *= f1;
            }

            #pragma unroll
            for (int nt = 0; nt < 8; nt++) {
                *(float2*)&sQP[(myr    ) * ATT_STRIDE + nt * 8 + 2 * tig] = make_float2(sacc[nt][0], sacc[nt][1]);
                *(float2*)&sQP[(myr + 8) * ATT_STRIDE + nt * 8 + 2 * tig] = make_float2(sacc[nt][2], sacc[nt][3]);
            }
            __syncwarp();

            #pragma unroll
            for (int ks = 0; ks < 8; ks++) {
                uint32_t pf[4];
                pf[0] = f2tf32(sQP[(myr    ) * ATT_STRIDE + ks * 8 + tig    ]);
                pf[1] = f2tf32(sQP[(myr + 8) * ATT_STRIDE + ks * 8 + tig    ]);
                pf[2] = f2tf32(sQP[(myr    ) * ATT_STRIDE + ks * 8 + tig + 4]);
                pf[3] = f2tf32(sQP[(myr + 8) * ATT_STRIDE + ks * 8 + tig + 4]);
                uint32_t vf[8][2];
                #pragma unroll
                for (int nt = 0; nt < 8; nt++) {
                    vf[nt][0] = __float_as_uint(sV[(ks * 8 + tig    ) * ATT_STRIDE + nt * 8 + grp]);
                    vf[nt][1] = __float_as_uint(sV[(ks * 8 + tig + 4) * ATT_STRIDE + nt * 8 + grp]);
                }
                #pragma unroll
                for (int nt = 0; nt < 8; nt++)
                    mma_tf32(oacc[nt], pf, vf[nt]);
            }
        }
        __syncthreads();
    }

    float inv0 = 1.0f / l0, inv1 = 1.0f / l1;
    float* obase = out + (size_t)(b * SS) * DD + h * HDIM;
    #pragma unroll
    for (int nt = 0; nt < 8; nt++) {
        int d = nt * 8 + 2 * tig;
        *(float2*)&obase[(size_t)row0 * DD + d] =
            make_float2(tf32r(oacc[nt][0] * inv0), tf32r(oacc[nt][1] * inv0));
        *(float2*)&obase[(size_t)row1 * DD + d] =
            make_float2(tf32r(oacc[nt][2] * inv1), tf32r(oacc[nt][3] * inv1));
    }
}

// ---------------- launch ----------------
extern "C" void kernel_launch(void* const* d_in, const int* in_sizes, int n_in,
                              void* d_out, int out_size)
{
    const float* x      = (const float*)d_in[0];
    const float* wq     = (const float*)d_in[1];
    const float* bq     = (const float*)d_in[2];
    const float* wk     = (const float*)d_in[3];
    const float* bk     = (const float*)d_in[4];
    const float* wv     = (const float*)d_in[5];
    const float* bv     = (const float*)d_in[6];
    const float* wo     = (const float*)d_in[7];
    const float* bo     = (const float*)d_in[8];
    const float* w_gate = (const float*)d_in[9];
    const float* w_up   = (const float*)d_in[10];
    const float* w_down = (const float*)d_in[11];
    const float* ln1w   = (const float*)d_in[12];
    const float* ln2w   = (const float*)d_in[13];
    float* out = (float*)d_out;

    static float *pH = nullptr, *pQKV, *pAtt, *pRes1, *pH2, *pGate, *pAct, *pCW, *pBcat;
    if (!pH) {
        cudaGetSymbolAddress((void**)&pH,    g_h);
        cudaGetSymbolAddress((void**)&pQKV,  g_qkv);
        cudaGetSymbolAddress((void**)&pAtt,  g_att);
        cudaGetSymbolAddress((void**)&pRes1, g_res1);
        cudaGetSymbolAddress((void**)&pH2,   g_h2);
        cudaGetSymbolAddress((void**)&pGate, g_gate);
        cudaGetSymbolAddress((void**)&pAct,  g_act);
        cudaGetSymbolAddress((void**)&pCW,   g_cw);
        cudaGetSymbolAddress((void**)&pBcat, g_bcat);
        cudaFuncSetAttribute(attn_kernel, cudaFuncAttributeMaxDynamicSharedMemorySize, ATT_SMEM_BYTES);
        cudaFuncSetAttribute(gemm_tf32_kernel, cudaFuncAttributeMaxDynamicSharedMemorySize, GEMM_SMEM_BYTES);
    }

    // 0. weight prep (RN rounding — required)
    const int nDD4 = DD * DD / 4, nDI4 = DD * II / 4;
    cvt_qkv_kernel<<<3 * nDD4 / 256, 256>>>(wq, wk, wv, pCW + CW_QKV);
    bcat_kernel<<<(LDQKV + 255) / 256, 256>>>(bq, bk, bv, pBcat);
    cvt_all_kernel<<<(nDD4 + 3 * nDI4 + 255) / 256, 256>>>(wo, w_gate, w_up, w_down, pCW);

    dim3 blk(256);
    const int RND = 1, NORND = 0;

    // 1. h = rmsnorm(x) (tf32)
    rmsnorm_kernel<<<MROWS, 256>>>(x, ln1w, pH);

    // 2. fused QKV projection (N=3072, tf32 out)
    dim3 gQKV(LDQKV / GBN, MROWS / GBM);               // 24 x 32
    gemm_tf32_kernel<<<gQKV, blk, GEMM_SMEM_BYTES>>>(pH, pCW + CW_QKV, pBcat, nullptr, nullptr, pQKV, MROWS, LDQKV, DD, RND);

    // 3. flash attention (LPT order)
    dim3 ga(SS / 128, HH, BB);
    attn_kernel<<<ga, 256, ATT_SMEM_BYTES>>>(pQKV, pAtt);

    // 4. res1 = att @ wo + bo + x
    dim3 gD(DD / GBN, MROWS / GBM);                    // 8 x 32
    gemm_tf32_kernel<<<gD, blk, GEMM_SMEM_BYTES>>>(pAtt, pCW + CW_O, bo, x, nullptr, pRes1, MROWS, DD, DD, NORND);

    // 5. h2 = rmsnorm(res1) (tf32)
    rmsnorm_kernel<<<MROWS, 256>>>(pRes1, ln2w, pH2);

    // 6. gate = h2 @ w_gate
    dim3 gI((II + GBN - 1) / GBN, MROWS / GBM);        // 30 x 32
    gemm_tf32_kernel<<<gI, blk, GEMM_SMEM_BYTES>>>(pH2, pCW + CW_G, nullptr, nullptr, nullptr, pGate, MROWS, II, DD, NORND);

    // 7. act = silu(gate) * (h2 @ w_up) (tf32)
    gemm_tf32_kernel<<<gI, blk, GEMM_SMEM_BYTES>>>(pH2, pCW + CW_U, nullptr, nullptr, pGate, pAct, MROWS, II, DD, RND);

    // 8. out = act @ w_down + res1
    gemm_tf32_kernel<<<gD, blk, GEMM_SMEM_BYTES>>>(pAct, pCW + CW_D, nullptr, pRes1, nullptr, out, MROWS, DD, II, NORND);
}

// round 11
// speedup vs baseline: 1.8584x; 1.6082x over previous
#include <cuda_runtime.h>
#include <cuda_fp16.h>
#include <math.h>
#include <stdint.h>

// Problem constants
#define BB 2
#define SS 2048
#define DD 1024
#define HH 16
#define HDIM 64
#define II 3752
#define MROWS (BB*SS)          // 4096
#define EPS 1e-6f
#define FULLMASK 0xffffffffu
#define LDQKV (3*DD)           // 3072

// ---------------- scratch (device globals) ----------------
__device__ __align__(16) __half g_h   [MROWS * DD];
__device__ float  g_qkv [MROWS * LDQKV];
__device__ __align__(16) __half g_att [MROWS * DD];
__device__ float  g_res1[MROWS * DD];
__device__ __align__(16) __half g_h2  [MROWS * DD];
__device__ float  g_gate[MROWS * II];
__device__ __align__(16) __half g_act [MROWS * II];
__device__ __align__(16) __half g_cw  [4 * DD * DD + 3 * DD * II];
__device__ float  g_bcat[LDQKV];

#define CW_QKV 0
#define CW_O  (3*DD*DD)
#define CW_G  (4*DD*DD)
#define CW_U  (4*DD*DD + DD*II)
#define CW_D  (4*DD*DD + 2*DD*II)

// ---------------- helpers ----------------
__device__ __forceinline__ uint32_t f2tf32(float f) {
    uint32_t r;
    asm("cvt.rna.tf32.f32 %0, %1;" : "=r"(r) : "f"(f));
    return r;
}
__device__ __forceinline__ float tf32r(float f) { return __uint_as_float(f2tf32(f)); }

__device__ __forceinline__ void mma_tf32(float* d, const uint32_t* a, const uint32_t* b) {
    asm("mma.sync.aligned.m16n8k8.row.col.f32.tf32.tf32.f32 "
        "{%0,%1,%2,%3},{%4,%5,%6,%7},{%8,%9},{%0,%1,%2,%3};"
        : "+f"(d[0]), "+f"(d[1]), "+f"(d[2]), "+f"(d[3])
        : "r"(a[0]), "r"(a[1]), "r"(a[2]), "r"(a[3]), "r"(b[0]), "r"(b[1]));
}

__device__ __forceinline__ void mma_f16(float* d, const uint32_t* a, const uint32_t* b) {
    asm("mma.sync.aligned.m16n8k16.row.col.f32.f16.f16.f32 "
        "{%0,%1,%2,%3},{%4,%5,%6,%7},{%8,%9},{%0,%1,%2,%3};"
        : "+f"(d[0]), "+f"(d[1]), "+f"(d[2]), "+f"(d[3])
        : "r"(a[0]), "r"(a[1]), "r"(a[2]), "r"(a[3]), "r"(b[0]), "r"(b[1]));
}

#define LDSM_X4(r, addr) \
    asm volatile("ldmatrix.sync.aligned.m8n8.x4.shared.b16 {%0,%1,%2,%3}, [%4];" \
        : "=r"((r)[0]), "=r"((r)[1]), "=r"((r)[2]), "=r"((r)[3]) : "r"(addr))
#define LDSM_X2T(r, addr) \
    asm volatile("ldmatrix.sync.aligned.m8n8.x2.trans.shared.b16 {%0,%1}, [%2];" \
        : "=r"((r)[0]), "=r"((r)[1]) : "r"(addr))

#define CP_ASYNC(dst, src, sz) \
    asm volatile("cp.async.cg.shared.global [%0], [%1], 16, %2;\n" :: "r"(dst), "l"(src), "r"(sz))
#define CP_COMMIT asm volatile("cp.async.commit_group;\n" ::)
#define CP_WAIT2  asm volatile("cp.async.wait_group 2;\n" ::)

// ---------------- weight converts (RN-round to fp16 once per replay) --------
__global__ void cvt_all_kernel(const float* __restrict__ wo, const float* __restrict__ wg,
                               const float* __restrict__ wu, const float* __restrict__ wd,
                               __half* __restrict__ cw)
{
    const int N_O = DD * DD / 4;
    const int N_I = DD * II / 4;
    int i = blockIdx.x * 256 + threadIdx.x;
    const float* src; __half* dst; int j;
    if (i < N_O)                  { src = wo; dst = cw + CW_O; j = i; }
    else if (i < N_O + N_I)       { src = wg; dst = cw + CW_G; j = i - N_O; }
    else if (i < N_O + 2 * N_I)   { src = wu; dst = cw + CW_U; j = i - N_O - N_I; }
    else if (i < N_O + 3 * N_I)   { src = wd; dst = cw + CW_D; j = i - N_O - 2 * N_I; }
    else return;
    float4 v = ((const float4*)src)[j];
    __half2* d2 = (__half2*)(dst + (size_t)j * 4);
    d2[0] = __floats2half2_rn(v.x, v.y);
    d2[1] = __floats2half2_rn(v.z, v.w);
}

// QKV: round + scatter into concat layout [K=1024][N=3072] (fp16)
__global__ void cvt_qkv_kernel(const float* __restrict__ wq, const float* __restrict__ wk,
                               const float* __restrict__ wv, __half* __restrict__ dst)
{
    const int PER = DD * DD / 4;
    int i = blockIdx.x * 256 + threadIdx.x;
    int which = i / PER;
    int j = i - which * PER;
    const float* src = (which == 0) ? wq : (which == 1) ? wk : wv;
    float4 v = ((const float4*)src)[j];
    int k = j >> 8;
    int n4 = j & 255;
    __half2* d2 = (__half2*)(dst + (size_t)k * LDQKV + which * DD + n4 * 4);
    d2[0] = __floats2half2_rn(v.x, v.y);
    d2[1] = __floats2half2_rn(v.z, v.w);
}

__global__ void bcat_kernel(const float* __restrict__ bq, const float* __restrict__ bk,
                            const float* __restrict__ bv, float* __restrict__ dst)
{
    int i = blockIdx.x * 256 + threadIdx.x;
    if (i < LDQKV) {
        int which = i >> 10, j = i & 1023;
        dst[i] = (which == 0) ? bq[j] : (which == 1) ? bk[j] : bv[j];
    }
}

// ---------------- RMSNorm (single pass, output fp16) ----------------
__global__ void rmsnorm_kernel(const float* __restrict__ x, const float* __restrict__ w,
                               __half* __restrict__ out)
{
    int row = blockIdx.x;
    int tid = threadIdx.x;
    float4 v = ((const float4*)(x + (size_t)row * DD))[tid];
    float sum = v.x * v.x + v.y * v.y + v.z * v.z + v.w * v.w;

    __shared__ float red[256];
    #pragma unroll
    for (int s = 16; s > 0; s >>= 1) sum += __shfl_xor_sync(FULLMASK, sum, s);
    if ((tid & 31) == 0) red[tid >> 5] = sum;
    __syncthreads();
    if (tid < 8) {
        float t = red[tid];
        #pragma unroll
        for (int s = 4; s > 0; s >>= 1) t += __shfl_xor_sync(0xFF, t, s);
        if (tid == 0) red[0] = t;
    }
    __syncthreads();
    float r = rsqrtf(red[0] * (1.0f / DD) + EPS);

    float4 wv = ((const float4*)w)[tid];
    __half2* o2 = (__half2*)(out + (size_t)row * DD + tid * 4);
    o2[0] = __floats2half2_rn(wv.x * (v.x * r), wv.y * (v.y * r));
    o2[1] = __floats2half2_rn(wv.z * (v.z * r), wv.w * (v.w * r));
}

// ---------------- pipelined fp16 GEMM: 128x128 block, warp 64x32, 4-stage ----
// A [M,K] fp16, W [K,N] fp16, fp32 accum. outmode: 0=f32, 1=f32 tf32-rounded, 2=f16
#define GBM 128
#define GBN 128
#define GBK 32          // halves per k-tile
#define NSTG 4
#define ASTRIDEH 40     // halves (80 B) — ldmatrix conflict-free
#define BSTRIDEH 136    // halves (272 B) — ldmatrix conflict-free
#define ASZH (GBM*ASTRIDEH)     // 5120 halves
#define BSZH (GBK*BSTRIDEH)     // 4352 halves
#define STGH (ASZH+BSZH)        // 9472 halves = 18944 B
#define GEMM_SMEM_BYTES (NSTG*STGH*2)

__device__ __forceinline__ void gemm_load_stage(
    const __half* __restrict__ A, const __half* __restrict__ W,
    int N, int K, int bm, int bn, int k0, uint32_t su, int tid)
{
    // A: 128 rows x 32 halves = 512 x 16B chunks
    #pragma unroll
    for (int u = 0; u < 2; u++) {
        int id = tid + u * 256;
        int row = id >> 2, ch = id & 3;
        int kk = k0 + ch * 8;
        int sz = (kk + 8 <= K) ? 16 : 0;
        const __half* src = A + (size_t)(bm + row) * K + (sz ? kk : 0);
        uint32_t dst = su + (row * ASTRIDEH + ch * 8) * 2;
        CP_ASYNC(dst, src, sz);
    }
    // B: 32 rows x 128 halves = 512 x 16B chunks
    #pragma unroll
    for (int u = 0; u < 2; u++) {
        int id = tid + u * 256;
        int row = id >> 4, ch = id & 15;
        int kk = k0 + row, col = bn + ch * 8;
        int sz = (kk < K && col + 8 <= N) ? 16 : 0;
        const __half* src = W + (sz ? ((size_t)kk * N + col) : 0);
        uint32_t dst = su + (ASZH + row * BSTRIDEH + ch * 8) * 2;
        CP_ASYNC(dst, src, sz);
    }
}

__global__ __launch_bounds__(256) void gemm_f16_kernel(
    const __half* __restrict__ A, const __half* __restrict__ W,
    const float* __restrict__ bias, const float* __restrict__ res,
    const float* __restrict__ gate, void* __restrict__ C,
    int M, int N, int K, int outmode)
{
    extern __shared__ __half smemh[];
    const uint32_t sbase = (uint32_t)__cvta_generic_to_shared(smemh);

    const int tid  = threadIdx.x;
    const int lane = tid & 31;
    const int warp = tid >> 5;
    const int wm = warp >> 2;            // 0..1 -> 64 rows
    const int wn = warp & 3;             // 0..3 -> 32 cols
    const int grp = lane >> 2;
    const int tig = lane & 3;

    const int bm = blockIdx.y * GBM;
    const int bn = blockIdx.x * GBN;

    float acc[4][4][4];
    #pragma unroll
    for (int i = 0; i < 4; i++)
        #pragma unroll
        for (int j = 0; j < 4; j++)
            #pragma unroll
            for (int r = 0; r < 4; r++) acc[i][j][r] = 0.f;

    const int T = (K + GBK - 1) / GBK;

    #pragma unroll
    for (int s = 0; s < 3; s++) {
        gemm_load_stage(A, W, N, K, bm, bn, s * GBK, sbase + s * STGH * 2, tid);
        CP_COMMIT;
    }

    // per-lane ldmatrix address components
    const int a_row = (lane & 15);            // row within 16-row frag
    const int a_koff = (lane >> 4) * 8;       // k offset 0/8
    const int b_krow = (lane & 15);           // k row within 16

    for (int t = 0; t < T; t++) {
        CP_WAIT2;
        __syncthreads();

        uint32_t su = sbase + (t % NSTG) * STGH * 2;
        uint32_t sa = su;
        uint32_t sb = su + ASZH * 2;

        #pragma unroll
        for (int ks = 0; ks < 2; ks++) {
            uint32_t af[4][4];
            #pragma unroll
            for (int mt = 0; mt < 4; mt++) {
                int row = wm * 64 + mt * 16 + a_row;
                uint32_t addr = sa + (row * ASTRIDEH + ks * 16 + a_koff) * 2;
                LDSM_X4(af[mt], addr);
            }
            uint32_t bf[4][2];
            #pragma unroll
            for (int nt = 0; nt < 4; nt++) {
                int krow = ks * 16 + b_krow;
                int n0 = wn * 32 + nt * 8;
                uint32_t addr = sb + (krow * BSTRIDEH + n0) * 2;
                LDSM_X2T(bf[nt], addr);
            }
            #pragma unroll
            for (int mt = 0; mt < 4; mt++)
                #pragma unroll
                for (int nt = 0; nt < 4; nt++)
                    mma_f16(acc[mt][nt], af[mt], bf[nt]);
        }

        if (t + 3 < T)
            gemm_load_stage(A, W, N, K, bm, bn, (t + 3) * GBK, sbase + ((t + 3) % NSTG) * STGH * 2, tid);
        CP_COMMIT;
    }

    // ---- epilogue ----
    #pragma unroll
    for (int mt = 0; mt < 4; mt++) {
        int r0 = bm + wm * 64 + mt * 16 + grp;
        #pragma unroll
        for (int nt = 0; nt < 4; nt++) {
            int c0 = bn + wn * 32 + nt * 8 + 2 * tig;
            if (c0 >= N) continue;
            float v0 = acc[mt][nt][0], v1 = acc[mt][nt][1];
            float v2 = acc[mt][nt][2], v3 = acc[mt][nt][3];
            if (bias) {
                float b0 = bias[c0], b1 = bias[c0 + 1];
                v0 += b0; v1 += b1; v2 += b0; v3 += b1;
            }
            if (gate) {
                float2 ga = *(const float2*)&gate[(size_t)r0 * N + c0];
                float2 gb = *(const float2*)&gate[(size_t)(r0 + 8) * N + c0];
                v0 *= ga.x / (1.0f + __expf(-ga.x));
                v1 *= ga.y / (1.0f + __expf(-ga.y));
                v2 *= gb.x / (1.0f + __expf(-gb.x));
                v3 *= gb.y / (1.0f + __expf(-gb.y));
            }
            if (res) {
                float2 ra = *(const float2*)&res[(size_t)r0 * N + c0];
                float2 rb = *(const float2*)&res[(size_t)(r0 + 8) * N + c0];
                v0 += ra.x; v1 += ra.y; v2 += rb.x; v3 += rb.y;
            }
            if (outmode == 2) {
                __half* Ch = (__half*)C;
                *(__half2*)&Ch[(size_t)r0 * N + c0]       = __floats2half2_rn(v0, v1);
                *(__half2*)&Ch[(size_t)(r0 + 8) * N + c0] = __floats2half2_rn(v2, v3);
            } else {
                if (outmode == 1) { v0 = tf32r(v0); v1 = tf32r(v1); v2 = tf32r(v2); v3 = tf32r(v3); }
                float* Cf = (float*)C;
                *(float2*)&Cf[(size_t)r0 * N + c0]       = make_float2(v0, v1);
                *(float2*)&Cf[(size_t)(r0 + 8) * N + c0] = make_float2(v2, v3);
            }
        }
    }
}

// ---------------- flash attention (tf32 mma, online softmax; fp16 output) ----
#define ATT_STRIDE 72
#define ATT_SMEM_BYTES ((64*ATT_STRIDE*2 + 128*ATT_STRIDE) * 4)

__global__ __launch_bounds__(256, 1) void attn_kernel(
    const float* __restrict__ qkv, __half* __restrict__ out)
{
    extern __shared__ float smem[];
    float* sK  = smem;
    float* sV  = smem + 64 * ATT_STRIDE;
    float* sQP = smem + 128 * ATT_STRIDE;

    const int tid  = threadIdx.x;
    const int lane = tid & 31;
    const int warp = tid >> 5;
    const int grp  = lane >> 2;
    const int tig  = lane & 3;

    const int qb = gridDim.x - 1 - blockIdx.x;    // LPT
    const int q0 = qb * 128;
    const int h  = blockIdx.y;
    const int b  = blockIdx.z;

    const float slope = -exp2f(-0.5f * (float)(h + 1));

    const float* qbase = qkv + (size_t)(b * SS + q0) * LDQKV + h * HDIM;
    #pragma unroll
    for (int it = 0; it < 8; it++) {
        int idx = it * 256 + tid;
        int r = idx >> 4, c4 = (idx & 15) * 4;
        *(float4*)&sQP[r * ATT_STRIDE + c4] = *(const float4*)&qbase[(size_t)r * LDQKV + c4];
    }
    __syncthreads();

    const int myr = warp * 16 + grp;
    uint32_t qf[8][4];
    #pragma unroll
    for (int ks = 0; ks < 8; ks++) {
        qf[ks][0] = __float_as_uint(0.125f * sQP[(myr    ) * ATT_STRIDE + ks * 8 + tig    ]);
        qf[ks][1] = __float_as_uint(0.125f * sQP[(myr + 8) * ATT_STRIDE + ks * 8 + tig    ]);
        qf[ks][2] = __float_as_uint(0.125f * sQP[(myr    ) * ATT_STRIDE + ks * 8 + tig + 4]);
        qf[ks][3] = __float_as_uint(0.125f * sQP[(myr + 8) * ATT_STRIDE + ks * 8 + tig + 4]);
    }
    __syncthreads();

    const int row0 = q0 + warp * 16 + grp;
    const int row1 = row0 + 8;
    const int warp_max_row = q0 + warp * 16 + 15;

    float m0 = -INFINITY, m1 = -INFINITY, l0 = 0.f, l1 = 0.f;
    float oacc[8][4];
    #pragma unroll
    for (int nt = 0; nt < 8; nt++)
        #pragma unroll
        for (int r = 0; r < 4; r++) oacc[nt][r] = 0.f;

    const int nkt = (q0 >> 6) + 2;
    const float* kbase0 = qkv + (size_t)(b * SS) * LDQKV + DD     + h * HDIM;
    const float* vbase0 = qkv + (size_t)(b * SS) * LDQKV + 2 * DD + h * HDIM;

    for (int kt = 0; kt < nkt; kt++) {
        const int j0 = kt * 64;
        const float* kb_ = kbase0 + (size_t)j0 * LDQKV;
        const float* vb_ = vbase0 + (size_t)j0 * LDQKV;
        #pragma unroll
        for (int it = 0; it < 4; it++) {
            int idx = it * 256 + tid;
            int r = idx >> 4, c4 = (idx & 15) * 4;
            *(float4*)&sK[r * ATT_STRIDE + c4] = *(const float4*)&kb_[(size_t)r * LDQKV + c4];
            *(float4*)&sV[r * ATT_STRIDE + c4] = *(const float4*)&vb_[(size_t)r * LDQKV + c4];
        }
        __syncthreads();

        if (j0 <= warp_max_row) {
            float sacc[8][4];
            #pragma unroll
            for (int nt = 0; nt < 8; nt++)
                #pragma unroll
                for (int r = 0; r < 4; r++) sacc[nt][r] = 0.f;

            #pragma unroll
            for (int ks = 0; ks < 8; ks++) {
                uint32_t bf[8][2];
                #pragma unroll
                for (int nt = 0; nt < 8; nt++) {
                    bf[nt][0] = __float_as_uint(sK[(nt * 8 + grp) * ATT_STRIDE + ks * 8 + tig    ]);
                    bf[nt][1] = __float_as_uint(sK[(nt * 8 + grp) * ATT_STRIDE + ks * 8 + tig + 4]);
                }
                #pragma unroll
                for (int nt = 0; nt < 8; nt++)
                    mma_tf32(sacc[nt], qf[ks], bf[nt]);
            }

            float mn0 = m0, mn1 = m1;
            #pragma unroll
            for (int nt = 0; nt < 8; nt++) {
                int cbase = j0 + nt * 8 + 2 * tig;
                #pragma unroll
                for (int r = 0; r < 4; r++) {
                    int col = cbase + (r & 1);
                    int rw = (r < 2) ? row0 : row1;
                    float s;
                    if (col > rw) s = -INFINITY;
                    else          s = sacc[nt][r] + slope * (float)(rw - col);
                    sacc[nt][r] = s;
                    if (r < 2) mn0 = fmaxf(mn0, s); else mn1 = fmaxf(mn1, s);
                }
            }
            mn0 = fmaxf(mn0, __shfl_xor_sync(FULLMASK, mn0, 1));
            mn0 = fmaxf(mn0, __shfl_xor_sync(FULLMASK, mn0, 2));
            mn1 = fmaxf(mn1, __shfl_xor_sync(FULLMASK, mn1, 1));
            mn1 = fmaxf(mn1, __shfl_xor_sync(FULLMASK, mn1, 2));

            float f0 = __expf(m0 - mn0);
            float f1 = __expf(m1 - mn1);
            m0 = mn0; m1 = mn1;

            float rs0 = 0.f, rs1 = 0.f;
            #pragma unroll
            for (int nt = 0; nt < 8; nt++) {
                float p0 = __expf(sacc[nt][0] - m0);
                float p1 = __expf(sacc[nt][1] - m0);
                float p2 = __expf(sacc[nt][2] - m1);
                float p3 = __expf(sacc[nt][3] - m1);
                sacc[nt][0] = p0; sacc[nt][1] = p1; sacc[nt][2] = p2; sacc[nt][3] = p3;
                rs0 += p0 + p1; rs1 += p2 + p3;
            }
            rs0 += __shfl_xor_sync(FULLMASK, rs0, 1);
            rs0 += __shfl_xor_sync(FULLMASK, rs0, 2);
            rs1 += __shfl_xor_sync(FULLMASK, rs1, 1);
            rs1 += __shfl_xor_sync(FULLMASK, rs1, 2);
            l0 = l0 * f0 + rs0;
            l1 = l1 * f1 + rs1;

            #pragma unroll
            for (int nt = 0; nt < 8; nt++) {
                oacc[nt][0] *= f0; oacc[nt][1] *= f0;
                oacc[nt][2] *= f1; oacc[nt][3] *= f1;
            }

            #pragma unroll
            for (int nt = 0; nt < 8; nt++) {
                *(float2*)&sQP[(myr    ) * ATT_STRIDE + nt * 8 + 2 * tig] = make_float2(sacc[nt][0], sacc[nt][1]);
                *(float2*)&sQP[(myr + 8) * ATT_STRIDE + nt * 8 + 2 * tig] = make_float2(sacc[nt][2], sacc[nt][3]);
            }
            __syncwarp();

            #pragma unroll
            for (int ks = 0; ks < 8; ks++) {
                uint32_t pf[4];
                pf[0] = f2tf32(sQP[(myr    ) * ATT_STRIDE + ks * 8 + tig    ]);
                pf[1] = f2tf32(sQP[(myr + 8) * ATT_STRIDE + ks * 8 + tig    ]);
                pf[2] = f2tf32(sQP[(myr    ) * ATT_STRIDE + ks * 8 + tig + 4]);
                pf[3] = f2tf32(sQP[(myr + 8) * ATT_STRIDE + ks * 8 + tig + 4]);
                uint32_t vf[8][2];
                #pragma unroll
                for (int nt = 0; nt < 8; nt++) {
                    vf[nt][0] = __float_as_uint(sV[(ks * 8 + tig    ) * ATT_STRIDE + nt * 8 + grp]);
                    vf[nt][1] = __float_as_uint(sV[(ks * 8 + tig + 4) * ATT_STRIDE + nt * 8 + grp]);
                }
                #pragma unroll
                for (int nt = 0; nt < 8; nt++)
                    mma_tf32(oacc[nt], pf, vf[nt]);
            }
        }
        __syncthreads();
    }

    float inv0 = 1.0f / l0, inv1 = 1.0f / l1;
    __half* obase = out + (size_t)(b * SS) * DD + h * HDIM;
    #pragma unroll
    for (int nt = 0; nt < 8; nt++) {
        int d = nt * 8 + 2 * tig;
        *(__half2*)&obase[(size_t)row0 * DD + d] =
            __floats2half2_rn(oacc[nt][0] * inv0, oacc[nt][1] * inv0);
        *(__half2*)&obase[(size_t)row1 * DD + d] =
            __floats2half2_rn(oacc[nt][2] * inv1, oacc[nt][3] * inv1);
    }
}

// ---------------- launch ----------------
extern "C" void kernel_launch(void* const* d_in, const int* in_sizes, int n_in,
                              void* d_out, int out_size)
{
    const float* x      = (const float*)d_in[0];
    const float* wq     = (const float*)d_in[1];
    const float* bq     = (const float*)d_in[2];
    const float* wk     = (const float*)d_in[3];
    const float* bk     = (const float*)d_in[4];
    const float* wv     = (const float*)d_in[5];
    const float* bv     = (const float*)d_in[6];
    const float* wo     = (const float*)d_in[7];
    const float* bo     = (const float*)d_in[8];
    const float* w_gate = (const float*)d_in[9];
    const float* w_up   = (const float*)d_in[10];
    const float* w_down = (const float*)d_in[11];
    const float* ln1w   = (const float*)d_in[12];
    const float* ln2w   = (const float*)d_in[13];
    float* out = (float*)d_out;

    static __half *pH = nullptr, *pAtt, *pH2, *pAct, *pCW;
    static float *pQKV, *pRes1, *pGate, *pBcat;
    if (!pH) {
        cudaGetSymbolAddress((void**)&pH,    g_h);
        cudaGetSymbolAddress((void**)&pQKV,  g_qkv);
        cudaGetSymbolAddress((void**)&pAtt,  g_att);
        cudaGetSymbolAddress((void**)&pRes1, g_res1);
        cudaGetSymbolAddress((void**)&pH2,   g_h2);
        cudaGetSymbolAddress((void**)&pGate, g_gate);
        cudaGetSymbolAddress((void**)&pAct,  g_act);
        cudaGetSymbolAddress((void**)&pCW,   g_cw);
        cudaGetSymbolAddress((void**)&pBcat, g_bcat);
        cudaFuncSetAttribute(attn_kernel, cudaFuncAttributeMaxDynamicSharedMemorySize, ATT_SMEM_BYTES);
        cudaFuncSetAttribute(gemm_f16_kernel, cudaFuncAttributeMaxDynamicSharedMemorySize, GEMM_SMEM_BYTES);
    }

    // 0. weight prep (RN rounding to fp16)
    const int nDD4 = DD * DD / 4, nDI4 = DD * II / 4;
    cvt_qkv_kernel<<<3 * nDD4 / 256, 256>>>(wq, wk, wv, pCW + CW_QKV);
    bcat_kernel<<<(LDQKV + 255) / 256, 256>>>(bq, bk, bv, pBcat);
    cvt_all_kernel<<<(nDD4 + 3 * nDI4 + 255) / 256, 256>>>(wo, w_gate, w_up, w_down, pCW);

    dim3 blk(256);

    // 1. h = rmsnorm(x) (fp16)
    rmsnorm_kernel<<<MROWS, 256>>>(x, ln1w, pH);

    // 2. fused QKV projection (out fp32, tf32-rounded for attention)
    dim3 gQKV(LDQKV / GBN, MROWS / GBM);               // 24 x 32
    gemm_f16_kernel<<<gQKV, blk, GEMM_SMEM_BYTES>>>(pH, pCW + CW_QKV, pBcat, nullptr, nullptr, pQKV, MROWS, LDQKV, DD, 1);

    // 3. flash attention (out fp16)
    dim3 ga(SS / 128, HH, BB);
    attn_kernel<<<ga, 256, ATT_SMEM_BYTES>>>(pQKV, pAtt);

    // 4. res1 = att @ wo + bo + x (fp32)
    dim3 gD(DD / GBN, MROWS / GBM);                    // 8 x 32
    gemm_f16_kernel<<<gD, blk, GEMM_SMEM_BYTES>>>(pAtt, pCW + CW_O, bo, x, nullptr, pRes1, MROWS, DD, DD, 0);

    // 5. h2 = rmsnorm(res1) (fp16)
    rmsnorm_kernel<<<MROWS, 256>>>(pRes1, ln2w, pH2);

    // 6. gate = h2 @ w_gate (fp32)
    dim3 gI((II + GBN - 1) / GBN, MROWS / GBM);        // 30 x 32
    gemm_f16_kernel<<<gI, blk, GEMM_SMEM_BYTES>>>(pH2, pCW + CW_G, nullptr, nullptr, nullptr, pGate, MROWS, II, DD, 0);

    // 7. act = silu(gate) * (h2 @ w_up) (fp16)
    gemm_f16_kernel<<<gI, blk, GEMM_SMEM_BYTES>>>(pH2, pCW + CW_U, nullptr, nullptr, pGate, pAct, MROWS, II, DD, 2);

    // 8. out = act @ w_down + res1 (fp32)
    gemm_f16_kernel<<<gD, blk, GEMM_SMEM_BYTES>>>(pAct, pCW + CW_D, nullptr, pRes1, nullptr, out, MROWS, DD, II, 0);
}

// round 12
// speedup vs baseline: 2.2568x; 1.2144x over previous
#include <cuda_runtime.h>
#include <cuda_fp16.h>
#include <math.h>
#include <stdint.h>

// Problem constants
#define BB 2
#define SS 2048
#define DD 1024
#define HH 16
#define HDIM 64
#define II 3752
#define MROWS (BB*SS)          // 4096
#define EPS 1e-6f
#define FULLMASK 0xffffffffu
#define LDQKV (3*DD)           // 3072

// ---------------- scratch (device globals) ----------------
__device__ __align__(16) __half g_h   [MROWS * DD];
__device__ __align__(16) __half g_qkv [MROWS * LDQKV];
__device__ __align__(16) __half g_att [MROWS * DD];
__device__ float  g_res1[MROWS * DD];
__device__ __align__(16) __half g_h2  [MROWS * DD];
__device__ float  g_gate[MROWS * II];
__device__ __align__(16) __half g_act [MROWS * II];
__device__ __align__(16) __half g_cw  [4 * DD * DD + 3 * DD * II];
__device__ float  g_bcat[LDQKV];

#define CW_QKV 0
#define CW_O  (3*DD*DD)
#define CW_G  (4*DD*DD)
#define CW_U  (4*DD*DD + DD*II)
#define CW_D  (4*DD*DD + 2*DD*II)

// ---------------- helpers ----------------
__device__ __forceinline__ void mma_f16(float* d, const uint32_t* a, const uint32_t* b) {
    asm("mma.sync.aligned.m16n8k16.row.col.f32.f16.f16.f32 "
        "{%0,%1,%2,%3},{%4,%5,%6,%7},{%8,%9},{%0,%1,%2,%3};"
        : "+f"(d[0]), "+f"(d[1]), "+f"(d[2]), "+f"(d[3])
        : "r"(a[0]), "r"(a[1]), "r"(a[2]), "r"(a[3]), "r"(b[0]), "r"(b[1]));
}

#define LDSM_X4(r, addr) \
    asm volatile("ldmatrix.sync.aligned.m8n8.x4.shared.b16 {%0,%1,%2,%3}, [%4];" \
        : "=r"((r)[0]), "=r"((r)[1]), "=r"((r)[2]), "=r"((r)[3]) : "r"(addr))
#define LDSM_X2(r, addr) \
    asm volatile("ldmatrix.sync.aligned.m8n8.x2.shared.b16 {%0,%1}, [%2];" \
        : "=r"((r)[0]), "=r"((r)[1]) : "r"(addr))
#define LDSM_X2T(r, addr) \
    asm volatile("ldmatrix.sync.aligned.m8n8.x2.trans.shared.b16 {%0,%1}, [%2];" \
        : "=r"((r)[0]), "=r"((r)[1]) : "r"(addr))

#define CP_ASYNC(dst, src, sz) \
    asm volatile("cp.async.cg.shared.global [%0], [%1], 16, %2;\n" :: "r"(dst), "l"(src), "r"(sz))
#define CP_COMMIT asm volatile("cp.async.commit_group;\n" ::)
#define CP_WAIT2  asm volatile("cp.async.wait_group 2;\n" ::)

// ---------------- weight converts (RN-round to fp16 once per replay) --------
__global__ void cvt_all_kernel(const float* __restrict__ wo, const float* __restrict__ wg,
                               const float* __restrict__ wu, const float* __restrict__ wd,
                               __half* __restrict__ cw)
{
    const int N_O = DD * DD / 4;
    const int N_I = DD * II / 4;
    int i = blockIdx.x * 256 + threadIdx.x;
    const float* src; __half* dst; int j;
    if (i < N_O)                  { src = wo; dst = cw + CW_O; j = i; }
    else if (i < N_O + N_I)       { src = wg; dst = cw + CW_G; j = i - N_O; }
    else if (i < N_O + 2 * N_I)   { src = wu; dst = cw + CW_U; j = i - N_O - N_I; }
    else if (i < N_O + 3 * N_I)   { src = wd; dst = cw + CW_D; j = i - N_O - 2 * N_I; }
    else return;
    float4 v = ((const float4*)src)[j];
    __half2* d2 = (__half2*)(dst + (size_t)j * 4);
    d2[0] = __floats2half2_rn(v.x, v.y);
    d2[1] = __floats2half2_rn(v.z, v.w);
}

__global__ void cvt_qkv_kernel(const float* __restrict__ wq, const float* __restrict__ wk,
                               const float* __restrict__ wv, __half* __restrict__ dst)
{
    const int PER = DD * DD / 4;
    int i = blockIdx.x * 256 + threadIdx.x;
    int which = i / PER;
    int j = i - which * PER;
    const float* src = (which == 0) ? wq : (which == 1) ? wk : wv;
    float4 v = ((const float4*)src)[j];
    int k = j >> 8;
    int n4 = j & 255;
    __half2* d2 = (__half2*)(dst + (size_t)k * LDQKV + which * DD + n4 * 4);
    d2[0] = __floats2half2_rn(v.x, v.y);
    d2[1] = __floats2half2_rn(v.z, v.w);
}

__global__ void bcat_kernel(const float* __restrict__ bq, const float* __restrict__ bk,
                            const float* __restrict__ bv, float* __restrict__ dst)
{
    int i = blockIdx.x * 256 + threadIdx.x;
    if (i < LDQKV) {
        int which = i >> 10, j = i & 1023;
        dst[i] = (which == 0) ? bq[j] : (which == 1) ? bk[j] : bv[j];
    }
}

// ---------------- RMSNorm (single pass, output fp16) ----------------
__global__ void rmsnorm_kernel(const float* __restrict__ x, const float* __restrict__ w,
                               __half* __restrict__ out)
{
    int row = blockIdx.x;
    int tid = threadIdx.x;
    float4 v = ((const float4*)(x + (size_t)row * DD))[tid];
    float sum = v.x * v.x + v.y * v.y + v.z * v.z + v.w * v.w;

    __shared__ float red[256];
    #pragma unroll
    for (int s = 16; s > 0; s >>= 1) sum += __shfl_xor_sync(FULLMASK, sum, s);
    if ((tid & 31) == 0) red[tid >> 5] = sum;
    __syncthreads();
    if (tid < 8) {
        float t = red[tid];
        #pragma unroll
        for (int s = 4; s > 0; s >>= 1) t += __shfl_xor_sync(0xFF, t, s);
        if (tid == 0) red[0] = t;
    }
    __syncthreads();
    float r = rsqrtf(red[0] * (1.0f / DD) + EPS);

    float4 wv = ((const float4*)w)[tid];
    __half2* o2 = (__half2*)(out + (size_t)row * DD + tid * 4);
    o2[0] = __floats2half2_rn(wv.x * (v.x * r), wv.y * (v.y * r));
    o2[1] = __floats2half2_rn(wv.z * (v.z * r), wv.w * (v.w * r));
}

// ---------------- pipelined fp16 GEMM: 128x128 block, warp 64x32, 4-stage ----
#define GBM 128
#define GBN 128
#define GBK 32
#define NSTG 4
#define ASTRIDEH 40
#define BSTRIDEH 136
#define ASZH (GBM*ASTRIDEH)
#define BSZH (GBK*BSTRIDEH)
#define STGH (ASZH+BSZH)
#define GEMM_SMEM_BYTES (NSTG*STGH*2)

__device__ __forceinline__ void gemm_load_stage(
    const __half* __restrict__ A, const __half* __restrict__ W,
    int N, int K, int bm, int bn, int k0, uint32_t su, int tid)
{
    #pragma unroll
    for (int u = 0; u < 2; u++) {
        int id = tid + u * 256;
        int row = id >> 2, ch = id & 3;
        int kk = k0 + ch * 8;
        int sz = (kk + 8 <= K) ? 16 : 0;
        const __half* src = A + (size_t)(bm + row) * K + (sz ? kk : 0);
        uint32_t dst = su + (row * ASTRIDEH + ch * 8) * 2;
        CP_ASYNC(dst, src, sz);
    }
    #pragma unroll
    for (int u = 0; u < 2; u++) {
        int id = tid + u * 256;
        int row = id >> 4, ch = id & 15;
        int kk = k0 + row, col = bn + ch * 8;
        int sz = (kk < K && col + 8 <= N) ? 16 : 0;
        const __half* src = W + (sz ? ((size_t)kk * N + col) : 0);
        uint32_t dst = su + (ASZH + row * BSTRIDEH + ch * 8) * 2;
        CP_ASYNC(dst, src, sz);
    }
}

__global__ __launch_bounds__(256) void gemm_f16_kernel(
    const __half* __restrict__ A, const __half* __restrict__ W,
    const float* __restrict__ bias, const float* __restrict__ res,
    const float* __restrict__ gate, void* __restrict__ C,
    int M, int N, int K, int outmode)   // 0=f32, 2=f16
{
    extern __shared__ __half smemh[];
    const uint32_t sbase = (uint32_t)__cvta_generic_to_shared(smemh);

    const int tid  = threadIdx.x;
    const int lane = tid & 31;
    const int warp = tid >> 5;
    const int wm = warp >> 2;
    const int wn = warp & 3;
    const int grp = lane >> 2;
    const int tig = lane & 3;

    const int bm = blockIdx.y * GBM;
    const int bn = blockIdx.x * GBN;

    float acc[4][4][4];
    #pragma unroll
    for (int i = 0; i < 4; i++)
        #pragma unroll
        for (int j = 0; j < 4; j++)
            #pragma unroll
            for (int r = 0; r < 4; r++) acc[i][j][r] = 0.f;

    const int T = (K + GBK - 1) / GBK;

    #pragma unroll
    for (int s = 0; s < 3; s++) {
        gemm_load_stage(A, W, N, K, bm, bn, s * GBK, sbase + s * STGH * 2, tid);
        CP_COMMIT;
    }

    const int a_row = (lane & 15);
    const int a_koff = (lane >> 4) * 8;
    const int b_krow = (lane & 15);

    for (int t = 0; t < T; t++) {
        CP_WAIT2;
        __syncthreads();

        uint32_t su = sbase + (t % NSTG) * STGH * 2;
        uint32_t sa = su;
        uint32_t sb = su + ASZH * 2;

        #pragma unroll
        for (int ks = 0; ks < 2; ks++) {
            uint32_t af[4][4];
            #pragma unroll
            for (int mt = 0; mt < 4; mt++) {
                int row = wm * 64 + mt * 16 + a_row;
                LDSM_X4(af[mt], sa + (row * ASTRIDEH + ks * 16 + a_koff) * 2);
            }
            uint32_t bf[4][2];
            #pragma unroll
            for (int nt = 0; nt < 4; nt++) {
                int krow = ks * 16 + b_krow;
                LDSM_X2T(bf[nt], sb + (krow * BSTRIDEH + wn * 32 + nt * 8) * 2);
            }
            #pragma unroll
            for (int mt = 0; mt < 4; mt++)
                #pragma unroll
                for (int nt = 0; nt < 4; nt++)
                    mma_f16(acc[mt][nt], af[mt], bf[nt]);
        }

        if (t + 3 < T)
            gemm_load_stage(A, W, N, K, bm, bn, (t + 3) * GBK, sbase + ((t + 3) % NSTG) * STGH * 2, tid);
        CP_COMMIT;
    }

    #pragma unroll
    for (int mt = 0; mt < 4; mt++) {
        int r0 = bm + wm * 64 + mt * 16 + grp;
        #pragma unroll
        for (int nt = 0; nt < 4; nt++) {
            int c0 = bn + wn * 32 + nt * 8 + 2 * tig;
            if (c0 >= N) continue;
            float v0 = acc[mt][nt][0], v1 = acc[mt][nt][1];
            float v2 = acc[mt][nt][2], v3 = acc[mt][nt][3];
            if (bias) {
                float b0 = bias[c0], b1 = bias[c0 + 1];
                v0 += b0; v1 += b1; v2 += b0; v3 += b1;
            }
            if (gate) {
                float2 ga = *(const float2*)&gate[(size_t)r0 * N + c0];
                float2 gb = *(const float2*)&gate[(size_t)(r0 + 8) * N + c0];
                v0 *= ga.x / (1.0f + __expf(-ga.x));
                v1 *= ga.y / (1.0f + __expf(-ga.y));
                v2 *= gb.x / (1.0f + __expf(-gb.x));
                v3 *= gb.y / (1.0f + __expf(-gb.y));
            }
            if (res) {
                float2 ra = *(const float2*)&res[(size_t)r0 * N + c0];
                float2 rb = *(const float2*)&res[(size_t)(r0 + 8) * N + c0];
                v0 += ra.x; v1 += ra.y; v2 += rb.x; v3 += rb.y;
            }
            if (outmode == 2) {
                __half* Ch = (__half*)C;
                *(__half2*)&Ch[(size_t)r0 * N + c0]       = __floats2half2_rn(v0, v1);
                *(__half2*)&Ch[(size_t)(r0 + 8) * N + c0] = __floats2half2_rn(v2, v3);
            } else {
                float* Cf = (float*)C;
                *(float2*)&Cf[(size_t)r0 * N + c0]       = make_float2(v0, v1);
                *(float2*)&Cf[(size_t)(r0 + 8) * N + c0] = make_float2(v2, v3);
            }
        }
    }
}

// ---------------- flash attention (fp16 mma, online softmax) ----------------
// qkv fp16 [M, 3072]; out fp16. smem tiles stride 72 halves (144 B).
#define ASH 72
#define ATT_SMEM_BYTES ((64*ASH*2 + 128*ASH) * 2)

__global__ __launch_bounds__(256) void attn_kernel(
    const __half* __restrict__ qkv, __half* __restrict__ out)
{
    extern __shared__ __half smh[];
    __half* sK  = smh;                  // 64 x 72
    __half* sV  = smh + 64 * ASH;       // 64 x 72
    __half* sQP = smh + 128 * ASH;      // 128 x 72 (Q staging, then P)
    const uint32_t sKu  = (uint32_t)__cvta_generic_to_shared(sK);
    const uint32_t sVu  = (uint32_t)__cvta_generic_to_shared(sV);
    const uint32_t sQPu = (uint32_t)__cvta_generic_to_shared(sQP);

    const int tid  = threadIdx.x;
    const int lane = tid & 31;
    const int warp = tid >> 5;
    const int grp  = lane >> 2;
    const int tig  = lane & 3;
    const int a_row  = lane & 15;
    const int a_koff = (lane >> 4) * 8;
    const int l15    = lane & 15;

    const int qb = gridDim.x - 1 - blockIdx.x;    // LPT
    const int q0 = qb * 128;
    const int h  = blockIdx.y;
    const int b  = blockIdx.z;

    const float slope = -exp2f(-0.5f * (float)(h + 1));
    const __half2 hscale = __float2half2_rn(0.125f);

    // ---- stage Q tile (scaled by 1/8, exact) ----
    const __half* qbase = qkv + (size_t)(b * SS + q0) * LDQKV + h * HDIM;
    #pragma unroll
    for (int it = 0; it < 4; it++) {
        int idx = it * 256 + tid;
        int r = idx >> 3, c8 = (idx & 7) * 8;
        uint4 raw = *(const uint4*)&qbase[(size_t)r * LDQKV + c8];
        __half2* p = (__half2*)&raw;
        p[0] = __hmul2(p[0], hscale); p[1] = __hmul2(p[1], hscale);
        p[2] = __hmul2(p[2], hscale); p[3] = __hmul2(p[3], hscale);
        *(uint4*)&sQP[r * ASH + c8] = raw;
    }
    __syncthreads();

    // ---- Q fragments: 4 k-chunks of 16 ----
    uint32_t qf[4][4];
    #pragma unroll
    for (int ks = 0; ks < 4; ks++)
        LDSM_X4(qf[ks], sQPu + ((warp * 16 + a_row) * ASH + ks * 16 + a_koff) * 2);
    __syncthreads();

    const int myr = warp * 16 + grp;
    const int row0 = q0 + warp * 16 + grp;
    const int row1 = row0 + 8;
    const int warp_max_row = q0 + warp * 16 + 15;

    float m0 = -INFINITY, m1 = -INFINITY, l0 = 0.f, l1 = 0.f;
    float oacc[8][4];
    #pragma unroll
    for (int nt = 0; nt < 8; nt++)
        #pragma unroll
        for (int r = 0; r < 4; r++) oacc[nt][r] = 0.f;

    const int nkt = (q0 >> 6) + 2;
    const __half* kbase0 = qkv + (size_t)(b * SS) * LDQKV + DD     + h * HDIM;
    const __half* vbase0 = qkv + (size_t)(b * SS) * LDQKV + 2 * DD + h * HDIM;

    for (int kt = 0; kt < nkt; kt++) {
        const int j0 = kt * 64;
        const __half* kb_ = kbase0 + (size_t)j0 * LDQKV;
        const __half* vb_ = vbase0 + (size_t)j0 * LDQKV;
        #pragma unroll
        for (int it = 0; it < 2; it++) {
            int idx = it * 256 + tid;
            int r = idx >> 3, c8 = (idx & 7) * 8;
            *(uint4*)&sK[r * ASH + c8] = *(const uint4*)&kb_[(size_t)r * LDQKV + c8];
            *(uint4*)&sV[r * ASH + c8] = *(const uint4*)&vb_[(size_t)r * LDQKV + c8];
        }
        __syncthreads();

        if (j0 <= warp_max_row) {
            // ---- S = Q @ K^T  (K [key][hd] == col-major B -> non-trans x2) ----
            float sacc[8][4];
            #pragma unroll
            for (int nt = 0; nt < 8; nt++)
                #pragma unroll
                for (int r = 0; r < 4; r++) sacc[nt][r] = 0.f;

            #pragma unroll
            for (int ks = 0; ks < 4; ks++) {
                #pragma unroll
                for (int nt = 0; nt < 8; nt++) {
                    uint32_t kf[2];
                    LDSM_X2(kf, sKu + ((nt * 8 + (l15 & 7)) * ASH + ks * 16 + (l15 >> 3) * 8) * 2);
                    mma_f16(sacc[nt], qf[ks], kf);
                }
            }

            // ---- bias + causal mask + online softmax ----
            float mn0 = m0, mn1 = m1;
            #pragma unroll
            for (int nt = 0; nt < 8; nt++) {
                int cbase = j0 + nt * 8 + 2 * tig;
                #pragma unroll
                for (int r = 0; r < 4; r++) {
                    int col = cbase + (r & 1);
                    int rw = (r < 2) ? row0 : row1;
                    float s;
                    if (col > rw) s = -INFINITY;
                    else          s = sacc[nt][r] + slope * (float)(rw - col);
                    sacc[nt][r] = s;
                    if (r < 2) mn0 = fmaxf(mn0, s); else mn1 = fmaxf(mn1, s);
                }
            }
            mn0 = fmaxf(mn0, __shfl_xor_sync(FULLMASK, mn0, 1));
            mn0 = fmaxf(mn0, __shfl_xor_sync(FULLMASK, mn0, 2));
            mn1 = fmaxf(mn1, __shfl_xor_sync(FULLMASK, mn1, 1));
            mn1 = fmaxf(mn1, __shfl_xor_sync(FULLMASK, mn1, 2));

            float f0 = __expf(m0 - mn0);
            float f1 = __expf(m1 - mn1);
            m0 = mn0; m1 = mn1;

            float rs0 = 0.f, rs1 = 0.f;
            #pragma unroll
            for (int nt = 0; nt < 8; nt++) {
                float p0 = __expf(sacc[nt][0] - m0);
                float p1 = __expf(sacc[nt][1] - m0);
                float p2 = __expf(sacc[nt][2] - m1);
                float p3 = __expf(sacc[nt][3] - m1);
                sacc[nt][0] = p0; sacc[nt][1] = p1; sacc[nt][2] = p2; sacc[nt][3] = p3;
                rs0 += p0 + p1; rs1 += p2 + p3;
            }
            rs0 += __shfl_xor_sync(FULLMASK, rs0, 1);
            rs0 += __shfl_xor_sync(FULLMASK, rs0, 2);
            rs1 += __shfl_xor_sync(FULLMASK, rs1, 1);
            rs1 += __shfl_xor_sync(FULLMASK, rs1, 2);
            l0 = l0 * f0 + rs0;
            l1 = l1 * f1 + rs1;

            #pragma unroll
            for (int nt = 0; nt < 8; nt++) {
                oacc[nt][0] *= f0; oacc[nt][1] *= f0;
                oacc[nt][2] *= f1; oacc[nt][3] *= f1;
            }

            // ---- P (fp16) -> warp-private smem ----
            #pragma unroll
            for (int nt = 0; nt < 8; nt++) {
                *(__half2*)&sQP[(myr    ) * ASH + nt * 8 + 2 * tig] = __floats2half2_rn(sacc[nt][0], sacc[nt][1]);
                *(__half2*)&sQP[(myr + 8) * ASH + nt * 8 + 2 * tig] = __floats2half2_rn(sacc[nt][2], sacc[nt][3]);
            }
            __syncwarp();

            // ---- O += P @ V  (V [key][hd] == row-major B -> x2.trans) ----
            #pragma unroll
            for (int ks = 0; ks < 4; ks++) {
                uint32_t pf[4];
                LDSM_X4(pf, sQPu + ((warp * 16 + a_row) * ASH + ks * 16 + a_koff) * 2);
                #pragma unroll
                for (int nt = 0; nt < 8; nt++) {
                    uint32_t vf[2];
                    LDSM_X2T(vf, sVu + ((ks * 16 + l15) * ASH + nt * 8) * 2);
                    mma_f16(oacc[nt], pf, vf);
                }
            }
        }
        __syncthreads();
    }

    float inv0 = 1.0f / l0, inv1 = 1.0f / l1;
    __half* obase = out + (size_t)(b * SS) * DD + h * HDIM;
    #pragma unroll
    for (int nt = 0; nt < 8; nt++) {
        int d = nt * 8 + 2 * tig;
        *(__half2*)&obase[(size_t)row0 * DD + d] =
            __floats2half2_rn(oacc[nt][0] * inv0, oacc[nt][1] * inv0);
        *(__half2*)&obase[(size_t)row1 * DD + d] =
            __floats2half2_rn(oacc[nt][2] * inv1, oacc[nt][3] * inv1);
    }
}

// ---------------- launch ----------------
extern "C" void kernel_launch(void* const* d_in, const int* in_sizes, int n_in,
                              void* d_out, int out_size)
{
    const float* x      = (const float*)d_in[0];
    const float* wq     = (const float*)d_in[1];
    const float* bq     = (const float*)d_in[2];
    const float* wk     = (const float*)d_in[3];
    const float* bk     = (const float*)d_in[4];
    const float* wv     = (const float*)d_in[5];
    const float* bv     = (const float*)d_in[6];
    const float* wo     = (const float*)d_in[7];
    const float* bo     = (const float*)d_in[8];
    const float* w_gate = (const float*)d_in[9];
    const float* w_up   = (const float*)d_in[10];
    const float* w_down = (const float*)d_in[11];
    const float* ln1w   = (const float*)d_in[12];
    const float* ln2w   = (const float*)d_in[13];
    float* out = (float*)d_out;

    static __half *pH = nullptr, *pQKV, *pAtt, *pH2, *pAct, *pCW;
    static float *pRes1, *pGate, *pBcat;
    if (!pH) {
        cudaGetSymbolAddress((void**)&pH,    g_h);
        cudaGetSymbolAddress((void**)&pQKV,  g_qkv);
        cudaGetSymbolAddress((void**)&pAtt,  g_att);
        cudaGetSymbolAddress((void**)&pRes1, g_res1);
        cudaGetSymbolAddress((void**)&pH2,   g_h2);
        cudaGetSymbolAddress((void**)&pGate, g_gate);
        cudaGetSymbolAddress((void**)&pAct,  g_act);
        cudaGetSymbolAddress((void**)&pCW,   g_cw);
        cudaGetSymbolAddress((void**)&pBcat, g_bcat);
        cudaFuncSetAttribute(attn_kernel, cudaFuncAttributeMaxDynamicSharedMemorySize, ATT_SMEM_BYTES);
        cudaFuncSetAttribute(gemm_f16_kernel, cudaFuncAttributeMaxDynamicSharedMemorySize, GEMM_SMEM_BYTES);
    }

    // 0. weight prep
    const int nDD4 = DD * DD / 4, nDI4 = DD * II / 4;
    cvt_qkv_kernel<<<3 * nDD4 / 256, 256>>>(wq, wk, wv, pCW + CW_QKV);
    bcat_kernel<<<(LDQKV + 255) / 256, 256>>>(bq, bk, bv, pBcat);
    cvt_all_kernel<<<(nDD4 + 3 * nDI4 + 255) / 256, 256>>>(wo, w_gate, w_up, w_down, pCW);

    dim3 blk(256);

    // 1. h = rmsnorm(x) (fp16)
    rmsnorm_kernel<<<MROWS, 256>>>(x, ln1w, pH);

    // 2. fused QKV projection (out fp16)
    dim3 gQKV(LDQKV / GBN, MROWS / GBM);
    gemm_f16_kernel<<<gQKV, blk, GEMM_SMEM_BYTES>>>(pH, pCW + CW_QKV, pBcat, nullptr, nullptr, pQKV, MROWS, LDQKV, DD, 2);

    // 3. flash attention (fp16 mma)
    dim3 ga(SS / 128, HH, BB);
    attn_kernel<<<ga, 256, ATT_SMEM_BYTES>>>(pQKV, pAtt);

    // 4. res1 = att @ wo + bo + x (fp32)
    dim3 gD(DD / GBN, MROWS / GBM);
    gemm_f16_kernel<<<gD, blk, GEMM_SMEM_BYTES>>>(pAtt, pCW + CW_O, bo, x, nullptr, pRes1, MROWS, DD, DD, 0);

    // 5. h2 = rmsnorm(res1) (fp16)
    rmsnorm_kernel<<<MROWS, 256>>>(pRes1, ln2w, pH2);

    // 6. gate = h2 @ w_gate (fp32)
    dim3 gI((II + GBN - 1) / GBN, MROWS / GBM);
    gemm_f16_kernel<<<gI, blk, GEMM_SMEM_BYTES>>>(pH2, pCW + CW_G, nullptr, nullptr, nullptr, pGate, MROWS, II, DD, 0);

    // 7. act = silu(gate) * (h2 @ w_up) (fp16)
    gemm_f16_kernel<<<gI, blk, GEMM_SMEM_BYTES>>>(pH2, pCW + CW_U, nullptr, nullptr, pGate, pAct, MROWS, II, DD, 2);

    // 8. out = act @ w_down + res1 (fp32)
    gemm_f16_kernel<<<gD, blk, GEMM_SMEM_BYTES>>>(pAct, pCW + CW_D, nullptr, pRes1, nullptr, out, MROWS, DD, II, 0);
}